// round 5
// baseline (speedup 1.0000x reference)
#include <cuda_runtime.h>
#include <cstdint>

#define N_SRC 200000
#define N_MID 100000
#define N_TGT 50000
#define D_IN  128
#define D_HID 256
#define D_OUT 64

// ---------------- scratch (device globals: no allocations allowed) ----------
__device__ float g_agg1[(size_t)N_MID * D_IN];   // 51.2 MB
__device__ float g_cnt1[N_MID];
__device__ float g_h[(size_t)N_MID * D_HID];     // 102.4 MB
__device__ float g_agg2[(size_t)N_TGT * D_HID];  // 51.2 MB
__device__ float g_cnt2[N_TGT];

// ---------------- zero the accumulators -------------------------------------
__global__ void zero_kernel() {
    size_t stride = (size_t)gridDim.x * blockDim.x;
    size_t i0 = (size_t)blockIdx.x * blockDim.x + threadIdx.x;
    float4 z = make_float4(0.f, 0.f, 0.f, 0.f);
    for (size_t i = i0; i < (size_t)N_MID * D_IN / 4; i += stride)
        reinterpret_cast<float4*>(g_agg1)[i] = z;
    for (size_t i = i0; i < (size_t)N_TGT * D_HID / 4; i += stride)
        reinterpret_cast<float4*>(g_agg2)[i] = z;
    for (size_t i = i0; i < N_MID / 4; i += stride)
        reinterpret_cast<float4*>(g_cnt1)[i] = z;
    for (size_t i = i0; i < N_TGT / 4; i += stride)
        reinterpret_cast<float4*>(g_cnt2)[i] = z;
}

// ---------------- edge scatter: warp per edge, vector RED -------------------
template <int D4>
__global__ void scatter_kernel(const float* __restrict__ feat,
                               const int* __restrict__ src,
                               const int* __restrict__ tgt,
                               int E,
                               float* __restrict__ agg,
                               float* __restrict__ cnt) {
    unsigned gtid = blockIdx.x * blockDim.x + threadIdx.x;
    int gw = (int)(gtid >> 5);
    if (gw >= E) return;
    int lane = threadIdx.x & 31;
    int s = __ldg(src + gw);
    int t = __ldg(tgt + gw);
    const float4* fs = reinterpret_cast<const float4*>(feat) + (size_t)s * D4;
    float4* ad = reinterpret_cast<float4*>(agg) + (size_t)t * D4;
#pragma unroll
    for (int c = lane; c < D4; c += 32) {
        float4 v = __ldg(fs + c);
        asm volatile("red.global.add.v4.f32 [%0], {%1,%2,%3,%4};"
                     :: "l"(ad + c), "f"(v.x), "f"(v.y), "f"(v.z), "f"(v.w)
                     : "memory");
    }
    if (lane == 0) atomicAdd(cnt + t, 1.0f);
}

// ---------------- mean normalization: agg[row] *= 1/max(cnt,1) --------------
template <int D4>
__global__ void norm_kernel(float* __restrict__ agg,
                            const float* __restrict__ cnt,
                            int rows) {
    int i = blockIdx.x * blockDim.x + threadIdx.x;   // one float4 per thread
    if (i >= rows * D4) return;
    int row = i / D4;
    float inv = 1.0f / fmaxf(__ldg(cnt + row), 1.0f);
    float4* p = reinterpret_cast<float4*>(agg) + i;
    float4 v = *p;
    v.x *= inv; v.y *= inv; v.z *= inv; v.w *= inv;
    *p = v;
}

// ---------------- concat-K SGEMM: C = [A0|A1] @ [B0;B1] + bias (opt ReLU) ---
// A0: [M, K1], A1: [M, K2], B0: [K1, N], B1: [K2, N], C: [M, N]
template <int BM, int BN, int BK, int TM, int TN, bool RELU>
__global__ void __launch_bounds__((BM / TM) * (BN / TN))
gemm_cat(int M, int N, int K1, int K2,
         const float* __restrict__ A0, const float* __restrict__ A1,
         const float* __restrict__ B0, const float* __restrict__ B1,
         const float* __restrict__ bias, float* __restrict__ C) {
    constexpr int NT = (BM / TM) * (BN / TN);
    constexpr int A4 = BM * BK / 4;   // float4 loads per A tile
    constexpr int B4 = BK * BN / 4;   // float4 loads per B tile

    __shared__ __align__(16) float As[BK][BM];
    __shared__ __align__(16) float Bs[BK][BN];

    const int tid = threadIdx.x;
    const int row0 = blockIdx.y * BM;
    const int col0 = blockIdx.x * BN;
    const int tr = (tid / (BN / TN)) * TM;
    const int tc = (tid % (BN / TN)) * TN;

    float acc[TM][TN];
#pragma unroll
    for (int i = 0; i < TM; i++)
#pragma unroll
        for (int j = 0; j < TN; j++) acc[i][j] = 0.f;

    const int K = K1 + K2;
    for (int kt = 0; kt < K; kt += BK) {
        // load A tile (float4 along K; K1, K2 are multiples of BK so a float4
        // never straddles the A0/A1 boundary)
        for (int i = tid; i < A4; i += NT) {
            int r = i / (BK / 4);
            int kq = (i % (BK / 4)) * 4;
            int gr = row0 + r;
            int gk = kt + kq;
            float4 v = make_float4(0.f, 0.f, 0.f, 0.f);
            if (gr < M) {
                const float* p = (gk < K1)
                    ? (A0 + (size_t)gr * K1 + gk)
                    : (A1 + (size_t)gr * K2 + (gk - K1));
                v = *reinterpret_cast<const float4*>(p);
            }
            As[kq + 0][r] = v.x; As[kq + 1][r] = v.y;
            As[kq + 2][r] = v.z; As[kq + 3][r] = v.w;
        }
        // load B tile
        for (int i = tid; i < B4; i += NT) {
            int kr = i / (BN / 4);
            int nq = (i % (BN / 4)) * 4;
            int gk = kt + kr;
            const float* p = (gk < K1)
                ? (B0 + (size_t)gk * N + col0 + nq)
                : (B1 + (size_t)(gk - K1) * N + col0 + nq);
            *reinterpret_cast<float4*>(&Bs[kr][nq]) =
                *reinterpret_cast<const float4*>(p);
        }
        __syncthreads();

#pragma unroll
        for (int k = 0; k < BK; k++) {
            float ra[TM], rb[TN];
#pragma unroll
            for (int i = 0; i < TM; i += 4)
                *reinterpret_cast<float4*>(&ra[i]) =
                    *reinterpret_cast<float4*>(&As[k][tr + i]);
#pragma unroll
            for (int j = 0; j < TN; j += 4)
                *reinterpret_cast<float4*>(&rb[j]) =
                    *reinterpret_cast<float4*>(&Bs[k][tc + j]);
#pragma unroll
            for (int i = 0; i < TM; i++)
#pragma unroll
                for (int j = 0; j < TN; j++)
                    acc[i][j] = fmaf(ra[i], rb[j], acc[i][j]);
        }
        __syncthreads();
    }

    // epilogue: bias (+ReLU), vectorized stores
#pragma unroll
    for (int i = 0; i < TM; i++) {
        int gr = row0 + tr + i;
        if (gr < M) {
#pragma unroll
            for (int j = 0; j < TN; j += 4) {
                float4 bb = *reinterpret_cast<const float4*>(&bias[col0 + tc + j]);
                float4 v;
                v.x = acc[i][j + 0] + bb.x;
                v.y = acc[i][j + 1] + bb.y;
                v.z = acc[i][j + 2] + bb.z;
                v.w = acc[i][j + 3] + bb.w;
                if (RELU) {
                    v.x = fmaxf(v.x, 0.f); v.y = fmaxf(v.y, 0.f);
                    v.z = fmaxf(v.z, 0.f); v.w = fmaxf(v.w, 0.f);
                }
                *reinterpret_cast<float4*>(&C[(size_t)gr * N + col0 + tc + j]) = v;
            }
        }
    }
}

// ---------------- launch ----------------------------------------------------
extern "C" void kernel_launch(void* const* d_in, const int* in_sizes, int n_in,
                              void* d_out, int out_size) {
    const float* x   = (const float*)d_in[0];
    const int*   ei1 = (const int*)d_in[1];
    const int*   ei2 = (const int*)d_in[2];
    const float* Wl1 = (const float*)d_in[3];
    const float* Wr1 = (const float*)d_in[4];
    const float* b1  = (const float*)d_in[5];
    const float* Wl2 = (const float*)d_in[6];
    const float* Wr2 = (const float*)d_in[7];
    const float* b2  = (const float*)d_in[8];
    float* out = (float*)d_out;

    const int E1 = in_sizes[1] / 2;
    const int E2 = in_sizes[2] / 2;

    float *agg1, *cnt1, *h, *agg2, *cnt2;
    cudaGetSymbolAddress((void**)&agg1, g_agg1);
    cudaGetSymbolAddress((void**)&cnt1, g_cnt1);
    cudaGetSymbolAddress((void**)&h,    g_h);
    cudaGetSymbolAddress((void**)&agg2, g_agg2);
    cudaGetSymbolAddress((void**)&cnt2, g_cnt2);

    // 1) zero accumulators
    zero_kernel<<<2048, 256>>>();

    // 2) layer-1 scatter: mean-sum x[src] into agg1[tgt], count into cnt1
    scatter_kernel<D_IN / 4><<<(unsigned)((E1 + 7) / 8), 256>>>(
        x, ei1, ei1 + E1, E1, agg1, cnt1);

    // 3) normalize agg1 by counts
    norm_kernel<D_IN / 4><<<(N_MID * (D_IN / 4) + 255) / 256, 256>>>(
        agg1, cnt1, N_MID);

    // 4) h = relu([agg1 | x[:N_MID]] @ [Wl1; Wr1] + b1)   [N_MID, 256]
    gemm_cat<128, 128, 8, 8, 8, true>
        <<<dim3(D_HID / 128, (N_MID + 127) / 128), 256>>>(
            N_MID, D_HID, D_IN, D_IN, agg1, x, Wl1, Wr1, b1, h);

    // 5) layer-2 scatter: h[src] into agg2[tgt], counts
    scatter_kernel<D_HID / 4><<<(unsigned)((E2 + 7) / 8), 256>>>(
        h, ei2, ei2 + E2, E2, agg2, cnt2);

    // 6) normalize agg2
    norm_kernel<D_HID / 4><<<(N_TGT * (D_HID / 4) + 255) / 256, 256>>>(
        agg2, cnt2, N_TGT);

    // 7) out = [agg2 | h[:N_TGT]] @ [Wl2; Wr2] + b2   [N_TGT, 64]
    gemm_cat<128, 64, 8, 8, 4, false>
        <<<dim3(D_OUT / 64, (N_TGT + 127) / 128), 256>>>(
            N_TGT, D_OUT, D_HID, D_HID, agg2, h, Wl2, Wr2, b2, out);
}

// round 7
// speedup vs baseline: 1.5689x; 1.5689x over previous
#include <cuda_runtime.h>
#include <cstdint>

#define N_SRC 200000
#define N_MID 100000
#define N_TGT 50000
#define D_IN  128
#define D_HID 256
#define D_OUT 64

// ---------------- scratch (device globals: no allocations allowed) ----------
__device__ float g_agg1[(size_t)N_MID * D_IN];   // 51.2 MB
__device__ float g_cnt1[N_MID];
__device__ float g_h[(size_t)N_MID * D_HID];     // 102.4 MB
__device__ float g_agg2[(size_t)N_TGT * D_HID];  // 51.2 MB
__device__ float g_cnt2[N_TGT];

// ---------------- zero the accumulators -------------------------------------
__global__ void zero_kernel() {
    size_t stride = (size_t)gridDim.x * blockDim.x;
    size_t i0 = (size_t)blockIdx.x * blockDim.x + threadIdx.x;
    float4 z = make_float4(0.f, 0.f, 0.f, 0.f);
    for (size_t i = i0; i < (size_t)N_MID * D_IN / 4; i += stride)
        reinterpret_cast<float4*>(g_agg1)[i] = z;
    for (size_t i = i0; i < (size_t)N_TGT * D_HID / 4; i += stride)
        reinterpret_cast<float4*>(g_agg2)[i] = z;
    for (size_t i = i0; i < N_MID / 4; i += stride)
        reinterpret_cast<float4*>(g_cnt1)[i] = z;
    for (size_t i = i0; i < N_TGT / 4; i += stride)
        reinterpret_cast<float4*>(g_cnt2)[i] = z;
}

// ---------------- edge scatter: warp per edge, vector RED -------------------
template <int D4>
__global__ void scatter_kernel(const float* __restrict__ feat,
                               const int* __restrict__ src,
                               const int* __restrict__ tgt,
                               int E,
                               float* __restrict__ agg,
                               float* __restrict__ cnt) {
    unsigned gtid = blockIdx.x * blockDim.x + threadIdx.x;
    int gw = (int)(gtid >> 5);
    if (gw >= E) return;
    int lane = threadIdx.x & 31;
    int s = __ldg(src + gw);
    int t = __ldg(tgt + gw);
    const float4* fs = reinterpret_cast<const float4*>(feat) + (size_t)s * D4;
    float4* ad = reinterpret_cast<float4*>(agg) + (size_t)t * D4;
#pragma unroll
    for (int c = lane; c < D4; c += 32) {
        float4 v = __ldg(fs + c);
        asm volatile("red.global.add.v4.f32 [%0], {%1,%2,%3,%4};"
                     :: "l"(ad + c), "f"(v.x), "f"(v.y), "f"(v.z), "f"(v.w)
                     : "memory");
    }
    if (lane == 0) atomicAdd(cnt + t, 1.0f);
}

// ---------------- mean normalization: agg[row] *= 1/max(cnt,1) --------------
template <int D4>
__global__ void norm_kernel(float* __restrict__ agg,
                            const float* __restrict__ cnt,
                            int rows) {
    int i = blockIdx.x * blockDim.x + threadIdx.x;   // one float4 per thread
    if (i >= rows * D4) return;
    int row = i / D4;
    float inv = 1.0f / fmaxf(__ldg(cnt + row), 1.0f);
    float4* p = reinterpret_cast<float4*>(agg) + i;
    float4 v = *p;
    v.x *= inv; v.y *= inv; v.z *= inv; v.w *= inv;
    *p = v;
}

// ---------------- tf32 tensor-core concat-K GEMM ----------------------------
// C[M,N] = [A0 | A1] @ [B0 ; B1] + bias, optional ReLU.
// A0:[M,K1] A1:[M,K2] row-major, B0:[K1,N] B1:[K2,N] row-major.
// mma.sync.m16n8k8 tf32, cp.async double-buffered, dynamic smem.
//
// PTX ISA m16n8k8.tf32 fragments (g = lane>>2, t = lane&3):
//   A: a0=(g,t) a1=(g+8,t) a2=(g,t+4) a3=(g+8,t+4)
//   B: b0=(k=t,n=g) b1=(k=t+4,n=g)
//   C: c0=(g,2t) c1=(g,2t+1) c2=(g+8,2t) c3=(g+8,2t+1)

__device__ __forceinline__ uint32_t f2tf(float x) {
    uint32_t r;
    asm("cvt.rna.tf32.f32 %0, %1;" : "=r"(r) : "f"(x));
    return r;
}

__device__ __forceinline__ void mma_tf32(float* c, const uint32_t* a,
                                         const uint32_t* b) {
    asm volatile(
        "mma.sync.aligned.m16n8k8.row.col.f32.tf32.tf32.f32 "
        "{%0,%1,%2,%3}, {%4,%5,%6,%7}, {%8,%9}, {%0,%1,%2,%3};"
        : "+f"(c[0]), "+f"(c[1]), "+f"(c[2]), "+f"(c[3])
        : "r"(a[0]), "r"(a[1]), "r"(a[2]), "r"(a[3]), "r"(b[0]), "r"(b[1]));
}

template <int BM, int BN, int BK, int WM, int WN, bool RELU>
__global__ void __launch_bounds__(256)
gemm_tf32(int M, int N, int K1, int K2,
          const float* __restrict__ A0, const float* __restrict__ A1,
          const float* __restrict__ B0, const float* __restrict__ B1,
          const float* __restrict__ bias, float* __restrict__ C) {
    constexpr int ASTR = BK + 4;   // ≡4 (mod 32): lanes (4g+t) conflict-free
    constexpr int BSTR = BN + 8;   // ≡8 (mod 32): lanes (8t+g) conflict-free
    constexpr int AS = BM * ASTR;
    constexpr int BS = BK * BSTR;
    constexpr int STAGE = AS + BS;
    constexpr int WARPS_M = BM / WM;
    constexpr int MT = WM / 16, NT = WN / 8;

    extern __shared__ float sm[];

    const int tid = threadIdx.x;
    const int warp = tid >> 5, lane = tid & 31;
    const int wm = warp % WARPS_M, wn = warp / WARPS_M;
    const int m0 = wm * WM, n0 = wn * WN;
    const int g = lane >> 2, t = lane & 3;
    const int row0 = blockIdx.y * BM, col0 = blockIdx.x * BN;
    const int K = K1 + K2;

    float acc[MT][NT][4];
#pragma unroll
    for (int i = 0; i < MT; i++)
#pragma unroll
        for (int j = 0; j < NT; j++)
#pragma unroll
            for (int r = 0; r < 4; r++) acc[i][j][r] = 0.f;

    // ---- async stage loader ----
    auto load_stage = [&](int kt, int s) {
        float* As = sm + s * STAGE;
        float* Bs = As + AS;
        constexpr int A4 = BM * BK / 4;
#pragma unroll
        for (int p = 0; p < A4 / 256; p++) {
            int idx = tid + p * 256;
            int r = idx / (BK / 4);
            int kq = (idx % (BK / 4)) * 4;
            int gr = row0 + r;
            int cr = gr < M ? gr : M - 1;        // clamp for addr safety
            int gk = kt + kq;
            const float* src = (gk < K1)
                ? (A0 + (size_t)cr * K1 + gk)
                : (A1 + (size_t)cr * K2 + (gk - K1));
            uint32_t dst = (uint32_t)__cvta_generic_to_shared(As + r * ASTR + kq);
            int sz = gr < M ? 16 : 0;
            asm volatile("cp.async.cg.shared.global [%0], [%1], 16, %2;"
                         :: "r"(dst), "l"(src), "r"(sz));
        }
        constexpr int B4 = BK * BN / 4;
#pragma unroll
        for (int p = 0; p < B4 / 256; p++) {
            int idx = tid + p * 256;
            int kr = idx / (BN / 4);
            int nq = (idx % (BN / 4)) * 4;
            int gk = kt + kr;
            const float* src = (gk < K1)
                ? (B0 + (size_t)gk * N + col0 + nq)
                : (B1 + (size_t)(gk - K1) * N + col0 + nq);
            uint32_t dst = (uint32_t)__cvta_generic_to_shared(Bs + kr * BSTR + nq);
            asm volatile("cp.async.cg.shared.global [%0], [%1], 16;"
                         :: "r"(dst), "l"(src));
        }
        asm volatile("cp.async.commit_group;");
    };

    // ---- per-stage compute ----
    auto compute = [&](int s) {
        const float* As = sm + s * STAGE;
        const float* Bs = As + AS;
#pragma unroll
        for (int ks = 0; ks < BK / 8; ks++) {
            const int k0 = ks * 8;
            uint32_t af[MT][4], bf[NT][2];
#pragma unroll
            for (int i = 0; i < MT; i++) {
                const float* a_lo = As + (m0 + 16 * i + g) * ASTR + k0;
                const float* a_hi = a_lo + 8 * ASTR;
                af[i][0] = f2tf(a_lo[t]);        // (g,   t)
                af[i][1] = f2tf(a_hi[t]);        // (g+8, t)
                af[i][2] = f2tf(a_lo[t + 4]);    // (g,   t+4)
                af[i][3] = f2tf(a_hi[t + 4]);    // (g+8, t+4)
            }
#pragma unroll
            for (int j = 0; j < NT; j++) {
                const float* bp = Bs + (k0 + t) * BSTR + n0 + 8 * j + g;
                bf[j][0] = f2tf(bp[0]);          // (k=t,   n=g)
                bf[j][1] = f2tf(bp[4 * BSTR]);   // (k=t+4, n=g)
            }
#pragma unroll
            for (int i = 0; i < MT; i++)
#pragma unroll
                for (int j = 0; j < NT; j++)
                    mma_tf32(acc[i][j], af[i], bf[j]);
        }
    };

    // ---- pipelined mainloop ----
    load_stage(0, 0);
    const int NKT = K / BK;
    for (int kt = 1; kt < NKT; kt++) {
        load_stage(kt * BK, kt & 1);
        asm volatile("cp.async.wait_group 1;");
        __syncthreads();
        compute((kt - 1) & 1);
        __syncthreads();
    }
    asm volatile("cp.async.wait_group 0;");
    __syncthreads();
    compute((NKT - 1) & 1);

    // ---- epilogue: bias (+ReLU), float2 stores ----
#pragma unroll
    for (int i = 0; i < MT; i++) {
#pragma unroll
        for (int j = 0; j < NT; j++) {
            const int col = col0 + n0 + 8 * j + 2 * t;
            const float2 bb = *reinterpret_cast<const float2*>(bias + col);
            float2 v0, v1;
            v0.x = acc[i][j][0] + bb.x; v0.y = acc[i][j][1] + bb.y;
            v1.x = acc[i][j][2] + bb.x; v1.y = acc[i][j][3] + bb.y;
            if (RELU) {
                v0.x = fmaxf(v0.x, 0.f); v0.y = fmaxf(v0.y, 0.f);
                v1.x = fmaxf(v1.x, 0.f); v1.y = fmaxf(v1.y, 0.f);
            }
            const int r1 = row0 + m0 + 16 * i + g;
            const int r2 = r1 + 8;
            if (r1 < M)
                *reinterpret_cast<float2*>(C + (size_t)r1 * N + col) = v0;
            if (r2 < M)
                *reinterpret_cast<float2*>(C + (size_t)r2 * N + col) = v1;
        }
    }
}

// ---------------- launch ----------------------------------------------------
extern "C" void kernel_launch(void* const* d_in, const int* in_sizes, int n_in,
                              void* d_out, int out_size) {
    const float* x   = (const float*)d_in[0];
    const int*   ei1 = (const int*)d_in[1];
    const int*   ei2 = (const int*)d_in[2];
    const float* Wl1 = (const float*)d_in[3];
    const float* Wr1 = (const float*)d_in[4];
    const float* b1  = (const float*)d_in[5];
    const float* Wl2 = (const float*)d_in[6];
    const float* Wr2 = (const float*)d_in[7];
    const float* b2  = (const float*)d_in[8];
    float* out = (float*)d_out;

    const int E1 = in_sizes[1] / 2;
    const int E2 = in_sizes[2] / 2;

    float *agg1, *cnt1, *h, *agg2, *cnt2;
    cudaGetSymbolAddress((void**)&agg1, g_agg1);
    cudaGetSymbolAddress((void**)&cnt1, g_cnt1);
    cudaGetSymbolAddress((void**)&h,    g_h);
    cudaGetSymbolAddress((void**)&agg2, g_agg2);
    cudaGetSymbolAddress((void**)&cnt2, g_cnt2);

    // GEMM1: BM=128 BN=128 BK=32 WM=64 WN=32
    // smem = 2 * (128*36 + 32*136) * 4 = 71680 B
    const int smem1 = 2 * (128 * 36 + 32 * 136) * (int)sizeof(float);
    cudaFuncSetAttribute(gemm_tf32<128, 128, 32, 64, 32, true>,
                         cudaFuncAttributeMaxDynamicSharedMemorySize, smem1);
    // GEMM2: BM=128 BN=64 BK=32 WM=64 WN=16
    // smem = 2 * (128*36 + 32*72) * 4 = 55296 B
    const int smem2 = 2 * (128 * 36 + 32 * 72) * (int)sizeof(float);
    cudaFuncSetAttribute(gemm_tf32<128, 64, 32, 64, 16, false>,
                         cudaFuncAttributeMaxDynamicSharedMemorySize, smem2);

    // 1) zero accumulators
    zero_kernel<<<2048, 256>>>();

    // 2) layer-1 scatter
    scatter_kernel<D_IN / 4><<<(unsigned)((E1 + 7) / 8), 256>>>(
        x, ei1, ei1 + E1, E1, agg1, cnt1);

    // 3) normalize agg1
    norm_kernel<D_IN / 4><<<(N_MID * (D_IN / 4) + 255) / 256, 256>>>(
        agg1, cnt1, N_MID);

    // 4) h = relu([agg1 | x[:N_MID]] @ [Wl1; Wr1] + b1)   [N_MID, 256]
    gemm_tf32<128, 128, 32, 64, 32, true>
        <<<dim3(D_HID / 128, (N_MID + 127) / 128), 256, smem1>>>(
            N_MID, D_HID, D_IN, D_IN, agg1, x, Wl1, Wr1, b1, h);

    // 5) layer-2 scatter
    scatter_kernel<D_HID / 4><<<(unsigned)((E2 + 7) / 8), 256>>>(
        h, ei2, ei2 + E2, E2, agg2, cnt2);

    // 6) normalize agg2
    norm_kernel<D_HID / 4><<<(N_TGT * (D_HID / 4) + 255) / 256, 256>>>(
        agg2, cnt2, N_TGT);

    // 7) out = [agg2 | h[:N_TGT]] @ [Wl2; Wr2] + b2   [N_TGT, 64]
    gemm_tf32<128, 64, 32, 64, 16, false>
        <<<dim3(D_OUT / 64, (N_TGT + 127) / 128), 256, smem2>>>(
            N_TGT, D_OUT, D_HID, D_HID, agg2, h, Wl2, Wr2, b2, out);
}

// round 9
// speedup vs baseline: 1.8693x; 1.1915x over previous
#include <cuda_runtime.h>
#include <cuda_fp16.h>
#include <cstdint>

#define N_SRC 200000
#define N_MID 100000
#define N_TGT 50000
#define D_IN  128
#define D_HID 256
#define D_OUT 64

// ---------------- scratch (device globals: no allocations allowed) ----------
__device__ __half g_xh[(size_t)N_SRC * D_IN];      // 51.2 MB fp16 copy of x (scatter gather)
__device__ float  g_xr[(size_t)N_MID * D_IN];      // 51.2 MB tf32-rounded x[:N_MID] (GEMM1 A1)
__device__ float  g_agg1[(size_t)N_MID * D_IN];    // 51.2 MB
__device__ float  g_cnt1[N_MID];
__device__ float  g_h[(size_t)N_MID * D_HID];      // 102.4 MB (tf32-rounded)
__device__ __half g_hw[(size_t)N_MID * D_OUT];     // 12.8 MB  h @ Wl2 in fp16
__device__ float  g_agg2[(size_t)N_TGT * D_OUT];   // 12.8 MB
__device__ float  g_cnt2[N_TGT];
__device__ float  g_W1[2 * D_IN * D_HID];          // [Wl1;Wr1] tf32-rounded
__device__ float  g_W2a[D_HID * D_OUT];            // Wl2 tf32
__device__ float  g_W2b[D_HID * D_OUT];            // Wr2 tf32

__device__ __forceinline__ uint32_t f2tf(float x) {
    uint32_t r;
    asm("cvt.rna.tf32.f32 %0, %1;" : "=r"(r) : "f"(x));
    return r;
}
__device__ __forceinline__ float tfr(float x) { return __uint_as_float(f2tf(x)); }

// ---------------- prep: x -> fp16 copy + tf32 copy ---------------------------
__global__ void prep_x(const float* __restrict__ x) {
    int i = blockIdx.x * blockDim.x + threadIdx.x;   // float4 id
    if (i >= N_SRC * (D_IN / 4)) return;
    float4 v = reinterpret_cast<const float4*>(x)[i];
    reinterpret_cast<__half2*>(g_xh)[i * 2]     = __floats2half2_rn(v.x, v.y);
    reinterpret_cast<__half2*>(g_xh)[i * 2 + 1] = __floats2half2_rn(v.z, v.w);
    if (i < N_MID * (D_IN / 4)) {
        float4 r;
        r.x = tfr(v.x); r.y = tfr(v.y); r.z = tfr(v.z); r.w = tfr(v.w);
        reinterpret_cast<float4*>(g_xr)[i] = r;
    }
}

// ---------------- prep: round weights to tf32 --------------------------------
__global__ void prep_w(const float* __restrict__ Wl1, const float* __restrict__ Wr1,
                       const float* __restrict__ Wl2, const float* __restrict__ Wr2) {
    int i = blockIdx.x * blockDim.x + threadIdx.x;
    const int n1 = D_IN * D_HID;
    if (i < 2 * n1)
        g_W1[i] = tfr(i < n1 ? Wl1[i] : Wr1[i - n1]);
    const int n2 = D_HID * D_OUT;
    if (i < n2) {
        g_W2a[i] = tfr(Wl2[i]);
        g_W2b[i] = tfr(Wr2[i]);
    }
}

// ---------------- zero the accumulators --------------------------------------
__global__ void zero_kernel() {
    size_t stride = (size_t)gridDim.x * blockDim.x;
    size_t i0 = (size_t)blockIdx.x * blockDim.x + threadIdx.x;
    float4 z = make_float4(0.f, 0.f, 0.f, 0.f);
    for (size_t i = i0; i < (size_t)N_MID * D_IN / 4; i += stride)
        reinterpret_cast<float4*>(g_agg1)[i] = z;
    for (size_t i = i0; i < (size_t)N_TGT * D_OUT / 4; i += stride)
        reinterpret_cast<float4*>(g_agg2)[i] = z;
    for (size_t i = i0; i < N_MID / 4; i += stride)
        reinterpret_cast<float4*>(g_cnt1)[i] = z;
    for (size_t i = i0; i < N_TGT / 4; i += stride)
        reinterpret_cast<float4*>(g_cnt2)[i] = z;
}

__device__ __forceinline__ void red4(float* p, float a, float b, float c, float d) {
    asm volatile("red.global.add.v4.f32 [%0], {%1,%2,%3,%4};"
                 :: "l"(p), "f"(a), "f"(b), "f"(c), "f"(d) : "memory");
}

// ---------------- scatter layer 1: fp16 gather, fp32 RED, 16 lanes/edge ------
__global__ void scatter1(const int* __restrict__ src, const int* __restrict__ tgt,
                         int E) {
    unsigned gtid = blockIdx.x * blockDim.x + threadIdx.x;
    int e = (int)(gtid >> 4);
    if (e >= E) return;
    int l = threadIdx.x & 15;
    int s = __ldg(src + e);
    int t = __ldg(tgt + e);
    uint4 d = __ldg(reinterpret_cast<const uint4*>(g_xh + (size_t)s * D_IN) + l);
    const __half2* hp = reinterpret_cast<const __half2*>(&d);
    float2 f0 = __half22float2(hp[0]), f1 = __half22float2(hp[1]);
    float2 f2 = __half22float2(hp[2]), f3 = __half22float2(hp[3]);
    float* ad = g_agg1 + (size_t)t * D_IN + l * 8;
    red4(ad,     f0.x, f0.y, f1.x, f1.y);
    red4(ad + 4, f2.x, f2.y, f3.x, f3.y);
    if (l == 0) atomicAdd(g_cnt1 + t, 1.0f);
}

// ---------------- scatter layer 2: gather hW fp16 (64-dim), 8 lanes/edge -----
__global__ void scatter2(const int* __restrict__ src, const int* __restrict__ tgt,
                         int E) {
    unsigned gtid = blockIdx.x * blockDim.x + threadIdx.x;
    int e = (int)(gtid >> 3);
    if (e >= E) return;
    int l = threadIdx.x & 7;
    int s = __ldg(src + e);
    int t = __ldg(tgt + e);
    uint4 d = __ldg(reinterpret_cast<const uint4*>(g_hw + (size_t)s * D_OUT) + l);
    const __half2* hp = reinterpret_cast<const __half2*>(&d);
    float2 f0 = __half22float2(hp[0]), f1 = __half22float2(hp[1]);
    float2 f2 = __half22float2(hp[2]), f3 = __half22float2(hp[3]);
    float* ad = g_agg2 + (size_t)t * D_OUT + l * 8;
    red4(ad,     f0.x, f0.y, f1.x, f1.y);
    red4(ad + 4, f2.x, f2.y, f3.x, f3.y);
    if (l == 0) atomicAdd(g_cnt2 + t, 1.0f);
}

// ---------------- norm1: agg1 *= 1/max(cnt,1), round to tf32 -----------------
__global__ void norm1_kernel() {
    int i = blockIdx.x * blockDim.x + threadIdx.x;   // one float4 per thread
    if (i >= N_MID * (D_IN / 4)) return;
    int row = i >> 5;                                // D_IN/4 = 32
    float inv = 1.0f / fmaxf(__ldg(g_cnt1 + row), 1.0f);
    float4* p = reinterpret_cast<float4*>(g_agg1) + i;
    float4 v = *p;
    v.x = tfr(v.x * inv); v.y = tfr(v.y * inv);
    v.z = tfr(v.z * inv); v.w = tfr(v.w * inv);
    *p = v;
}

// ---------------- tf32 tensor-core GEMM (operands pre-rounded to tf32) -------
// C[M,N] = [A0 | A1] @ B (+bias) (+ReLU), A0:[M,K1], A1:[M,K-K1], B:[K,N].
// EPI: 0 = fp32 store, 1 = tf32-rounded fp32 store, 2 = fp16 store,
//      3 = fp32 store + agg[r][c]/max(cnt[r],1) added.
__device__ __forceinline__ void mma_tf32(float* c, const uint32_t* a,
                                         const uint32_t* b) {
    asm volatile(
        "mma.sync.aligned.m16n8k8.row.col.f32.tf32.tf32.f32 "
        "{%0,%1,%2,%3}, {%4,%5,%6,%7}, {%8,%9}, {%0,%1,%2,%3};"
        : "+f"(c[0]), "+f"(c[1]), "+f"(c[2]), "+f"(c[3])
        : "r"(a[0]), "r"(a[1]), "r"(a[2]), "r"(a[3]), "r"(b[0]), "r"(b[1]));
}

template <int BM, int BN, int BK, int WM, int WN, bool RELU, int EPI, bool BIAS>
__global__ void __launch_bounds__(256, 1)
gemm_tf32(int M, int Nn, int K, int K1,
          const float* __restrict__ A0, const float* __restrict__ A1,
          const float* __restrict__ B, const float* __restrict__ bias,
          float* __restrict__ Cf, __half* __restrict__ Ch,
          const float* __restrict__ aggp, const float* __restrict__ cntp) {
    constexpr int ASTR = BK + 4;   // ≡4 (mod 32): lanes (4g+t) conflict-free
    constexpr int BSTR = BN + 8;   // ≡8 (mod 32): lanes (8t+g) conflict-free
    constexpr int AS = BM * ASTR;
    constexpr int BS = BK * BSTR;
    constexpr int STAGE = AS + BS;
    constexpr int WARPS_M = BM / WM;
    constexpr int MT = WM / 16, NT = WN / 8;

    extern __shared__ float sm[];

    const int tid = threadIdx.x;
    const int warp = tid >> 5, lane = tid & 31;
    const int wm = warp % WARPS_M, wn = warp / WARPS_M;
    const int m0 = wm * WM, n0 = wn * WN;
    const int g = lane >> 2, t = lane & 3;
    const int row0 = blockIdx.y * BM, col0 = blockIdx.x * BN;
    const int K2s = K - K1;

    float acc[MT][NT][4];
#pragma unroll
    for (int i = 0; i < MT; i++)
#pragma unroll
        for (int j = 0; j < NT; j++)
#pragma unroll
            for (int r = 0; r < 4; r++) acc[i][j][r] = 0.f;

    auto load_stage = [&](int kt, int s) {
        float* As = sm + s * STAGE;
        float* Bs = As + AS;
        constexpr int A4 = BM * BK / 4;
#pragma unroll
        for (int p = 0; p < A4 / 256; p++) {
            int idx = tid + p * 256;
            int r = idx / (BK / 4);
            int kq = (idx % (BK / 4)) * 4;
            int gr = row0 + r;
            int cr = gr < M ? gr : M - 1;
            int gk = kt + kq;
            const float* src = (gk < K1)
                ? (A0 + (size_t)cr * K1 + gk)
                : (A1 + (size_t)cr * K2s + (gk - K1));
            uint32_t dst = (uint32_t)__cvta_generic_to_shared(As + r * ASTR + kq);
            int sz = gr < M ? 16 : 0;
            asm volatile("cp.async.cg.shared.global [%0], [%1], 16, %2;"
                         :: "r"(dst), "l"(src), "r"(sz));
        }
        constexpr int B4 = BK * BN / 4;
#pragma unroll
        for (int p = 0; p < B4 / 256; p++) {
            int idx = tid + p * 256;
            int kr = idx / (BN / 4);
            int nq = (idx % (BN / 4)) * 4;
            const float* src = B + (size_t)(kt + kr) * Nn + col0 + nq;
            uint32_t dst = (uint32_t)__cvta_generic_to_shared(Bs + kr * BSTR + nq);
            asm volatile("cp.async.cg.shared.global [%0], [%1], 16;"
                         :: "r"(dst), "l"(src));
        }
        asm volatile("cp.async.commit_group;");
    };

    auto compute = [&](int s) {
        const float* As = sm + s * STAGE;
        const float* Bs = As + AS;
#pragma unroll
        for (int ks = 0; ks < BK / 8; ks++) {
            const int k0 = ks * 8;
            uint32_t af[MT][4], bf[NT][2];
#pragma unroll
            for (int i = 0; i < MT; i++) {
                const float* a_lo = As + (m0 + 16 * i + g) * ASTR + k0;
                const float* a_hi = a_lo + 8 * ASTR;
                af[i][0] = __float_as_uint(a_lo[t]);
                af[i][1] = __float_as_uint(a_hi[t]);
                af[i][2] = __float_as_uint(a_lo[t + 4]);
                af[i][3] = __float_as_uint(a_hi[t + 4]);
            }
#pragma unroll
            for (int j = 0; j < NT; j++) {
                const float* bp = Bs + (k0 + t) * BSTR + n0 + 8 * j + g;
                bf[j][0] = __float_as_uint(bp[0]);
                bf[j][1] = __float_as_uint(bp[4 * BSTR]);
            }
#pragma unroll
            for (int i = 0; i < MT; i++)
#pragma unroll
                for (int j = 0; j < NT; j++)
                    mma_tf32(acc[i][j], af[i], bf[j]);
        }
    };

    load_stage(0, 0);
    const int NKT = K / BK;
    for (int kt = 1; kt < NKT; kt++) {
        load_stage(kt * BK, kt & 1);
        asm volatile("cp.async.wait_group 1;");
        __syncthreads();
        compute((kt - 1) & 1);
        __syncthreads();
    }
    asm volatile("cp.async.wait_group 0;");
    __syncthreads();
    compute((NKT - 1) & 1);

    // ---- epilogue ----
#pragma unroll
    for (int i = 0; i < MT; i++) {
        const int r1 = row0 + m0 + 16 * i + g;
        const int r2 = r1 + 8;
        float inv1 = 0.f, inv2 = 0.f;
        if (EPI == 3) {
            inv1 = r1 < M ? 1.0f / fmaxf(__ldg(cntp + r1), 1.0f) : 0.f;
            inv2 = r2 < M ? 1.0f / fmaxf(__ldg(cntp + r2), 1.0f) : 0.f;
        }
#pragma unroll
        for (int j = 0; j < NT; j++) {
            const int col = col0 + n0 + 8 * j + 2 * t;
            float2 bb = make_float2(0.f, 0.f);
            if (BIAS)
                bb = *reinterpret_cast<const float2*>(bias + col);
            float2 v0, v1;
            v0.x = acc[i][j][0] + bb.x; v0.y = acc[i][j][1] + bb.y;
            v1.x = acc[i][j][2] + bb.x; v1.y = acc[i][j][3] + bb.y;
            if (EPI == 3) {
                if (r1 < M) {
                    float2 a = *reinterpret_cast<const float2*>(
                        aggp + (size_t)r1 * Nn + col);
                    v0.x += a.x * inv1; v0.y += a.y * inv1;
                }
                if (r2 < M) {
                    float2 a = *reinterpret_cast<const float2*>(
                        aggp + (size_t)r2 * Nn + col);
                    v1.x += a.x * inv2; v1.y += a.y * inv2;
                }
            }
            if (RELU) {
                v0.x = fmaxf(v0.x, 0.f); v0.y = fmaxf(v0.y, 0.f);
                v1.x = fmaxf(v1.x, 0.f); v1.y = fmaxf(v1.y, 0.f);
            }
            if (EPI == 1) {
                v0.x = tfr(v0.x); v0.y = tfr(v0.y);
                v1.x = tfr(v1.x); v1.y = tfr(v1.y);
            }
            if (EPI == 2) {
                if (r1 < M)
                    *reinterpret_cast<__half2*>(Ch + (size_t)r1 * Nn + col) =
                        __floats2half2_rn(v0.x, v0.y);
                if (r2 < M)
                    *reinterpret_cast<__half2*>(Ch + (size_t)r2 * Nn + col) =
                        __floats2half2_rn(v1.x, v1.y);
            } else {
                if (r1 < M)
                    *reinterpret_cast<float2*>(Cf + (size_t)r1 * Nn + col) = v0;
                if (r2 < M)
                    *reinterpret_cast<float2*>(Cf + (size_t)r2 * Nn + col) = v1;
            }
        }
    }
}

// ---------------- launch -----------------------------------------------------
extern "C" void kernel_launch(void* const* d_in, const int* in_sizes, int n_in,
                              void* d_out, int out_size) {
    const float* x   = (const float*)d_in[0];
    const int*   ei1 = (const int*)d_in[1];
    const int*   ei2 = (const int*)d_in[2];
    const float* Wl1 = (const float*)d_in[3];
    const float* Wr1 = (const float*)d_in[4];
    const float* b1  = (const float*)d_in[5];
    const float* Wl2 = (const float*)d_in[6];
    const float* Wr2 = (const float*)d_in[7];
    const float* b2  = (const float*)d_in[8];
    float* out = (float*)d_out;

    const int E1 = in_sizes[1] / 2;
    const int E2 = in_sizes[2] / 2;

    float *agg1, *cnt1, *h, *agg2, *cnt2, *xr, *W1, *W2a, *W2b;
    __half *hw;
    cudaGetSymbolAddress((void**)&agg1, g_agg1);
    cudaGetSymbolAddress((void**)&cnt1, g_cnt1);
    cudaGetSymbolAddress((void**)&h,    g_h);
    cudaGetSymbolAddress((void**)&agg2, g_agg2);
    cudaGetSymbolAddress((void**)&cnt2, g_cnt2);
    cudaGetSymbolAddress((void**)&xr,   g_xr);
    cudaGetSymbolAddress((void**)&W1,   g_W1);
    cudaGetSymbolAddress((void**)&W2a,  g_W2a);
    cudaGetSymbolAddress((void**)&W2b,  g_W2b);
    cudaGetSymbolAddress((void**)&hw,   g_hw);

    // GEMM1: BM=128 BN=256 BK=32 WM=64 WN=64, 8 warps
    // smem = 2*(128*36 + 32*264)*4 = 104448 B
    const int smem1 = 2 * (128 * 36 + 32 * 264) * (int)sizeof(float);
    cudaFuncSetAttribute(gemm_tf32<128, 256, 32, 64, 64, true, 1, true>,
                         cudaFuncAttributeMaxDynamicSharedMemorySize, smem1);
    // GEMM_hW / GEMM_out: BM=128 BN=64 BK=32 WM=32 WN=32
    // smem = 2*(128*36 + 32*72)*4 = 55296 B
    const int smem2 = 2 * (128 * 36 + 32 * 72) * (int)sizeof(float);
    cudaFuncSetAttribute(gemm_tf32<128, 64, 32, 32, 32, false, 2, false>,
                         cudaFuncAttributeMaxDynamicSharedMemorySize, smem2);
    cudaFuncSetAttribute(gemm_tf32<128, 64, 32, 32, 32, false, 3, true>,
                         cudaFuncAttributeMaxDynamicSharedMemorySize, smem2);

    // 1) prep: x -> fp16 + tf32 copies; weights -> tf32
    prep_x<<<(N_SRC * (D_IN / 4) + 255) / 256, 256>>>(x);
    prep_w<<<(2 * D_IN * D_HID + 255) / 256, 256>>>(Wl1, Wr1, Wl2, Wr2);

    // 2) zero accumulators
    zero_kernel<<<2048, 256>>>();

    // 3) layer-1 scatter (16 lanes/edge, fp16 gather)
    scatter1<<<(unsigned)(((size_t)E1 * 16 + 255) / 256), 256>>>(ei1, ei1 + E1, E1);

    // 4) normalize agg1 (+ tf32 round)
    norm1_kernel<<<(N_MID * (D_IN / 4) + 255) / 256, 256>>>();

    // 5) h = relu([agg1 | xr] @ W1 + b1), stored tf32-rounded  [N_MID, 256]
    gemm_tf32<128, 256, 32, 64, 64, true, 1, true>
        <<<dim3(1, (N_MID + 127) / 128), 256, smem1>>>(
            N_MID, D_HID, 2 * D_IN, D_IN, agg1, xr, W1, b1, h, nullptr,
            nullptr, nullptr);

    // 6) hW = h @ Wl2, stored fp16  [N_MID, 64]
    gemm_tf32<128, 64, 32, 32, 32, false, 2, false>
        <<<dim3(1, (N_MID + 127) / 128), 256, smem2>>>(
            N_MID, D_OUT, D_HID, D_HID, h, h, W2a, nullptr, nullptr, hw,
            nullptr, nullptr);

    // 7) layer-2 scatter on 64-dim hW (8 lanes/edge)
    scatter2<<<(unsigned)(((size_t)E2 * 8 + 255) / 256), 256>>>(ei2, ei2 + E2, E2);

    // 8) out = h[:N_TGT] @ Wr2 + b2 + agg2/max(cnt2,1)   [N_TGT, 64]
    gemm_tf32<128, 64, 32, 32, 32, false, 3, true>
        <<<dim3(1, (N_TGT + 127) / 128), 256, smem2>>>(
            N_TGT, D_OUT, D_HID, D_HID, h, h, W2b, b2, out, nullptr,
            agg2, cnt2);
}

// round 11
// speedup vs baseline: 2.7919x; 1.4935x over previous
#include <cuda_runtime.h>
#include <cuda_fp16.h>
#include <cstdint>

#define N_SRC 200000
#define N_MID 100000
#define N_TGT 50000
#define D_IN  128
#define D_HID 256
#define D_OUT 64
#define E1_MAX 1600000
#define E2_MAX 800000

// ---------------- scratch (device globals: no allocations allowed) ----------
__device__ __half g_xh[(size_t)N_SRC * D_IN];      // 51.2 MB fp16 copy of x
__device__ float  g_xr[(size_t)N_MID * D_IN];      // tf32-rounded x[:N_MID]
__device__ float  g_agg1[(size_t)N_MID * D_IN];    // normalized mean, tf32
__device__ float  g_h[(size_t)N_MID * D_HID];      // tf32-rounded
__device__ __half g_hw[(size_t)N_MID * D_OUT];     // h @ Wl2 in fp16
__device__ float  g_agg2[(size_t)N_TGT * D_OUT];   // normalized mean
__device__ float  g_W1[2 * D_IN * D_HID];
__device__ float  g_W2a[D_HID * D_OUT];
__device__ float  g_W2b[D_HID * D_OUT];
// CSR build scratch
__device__ int    g_deg1[N_MID],  g_roff1[N_MID],  g_woff1[N_MID];
__device__ int    g_deg2[N_TGT],  g_roff2[N_TGT],  g_woff2[N_TGT];
__device__ int    g_sums1[512],   g_sums2[512];
__device__ int    g_sorted1[E1_MAX], g_sorted2[E2_MAX];

__device__ __forceinline__ uint32_t f2tf(float x) {
    uint32_t r;
    asm("cvt.rna.tf32.f32 %0, %1;" : "=r"(r) : "f"(x));
    return r;
}
__device__ __forceinline__ float tfr(float x) { return __uint_as_float(f2tf(x)); }

// ---------------- prep: x -> fp16 copy + tf32 copy ---------------------------
__global__ void prep_x(const float* __restrict__ x) {
    int i = blockIdx.x * blockDim.x + threadIdx.x;   // float4 id
    if (i >= N_SRC * (D_IN / 4)) return;
    float4 v = reinterpret_cast<const float4*>(x)[i];
    reinterpret_cast<__half2*>(g_xh)[i * 2]     = __floats2half2_rn(v.x, v.y);
    reinterpret_cast<__half2*>(g_xh)[i * 2 + 1] = __floats2half2_rn(v.z, v.w);
    if (i < N_MID * (D_IN / 4)) {
        float4 r;
        r.x = tfr(v.x); r.y = tfr(v.y); r.z = tfr(v.z); r.w = tfr(v.w);
        reinterpret_cast<float4*>(g_xr)[i] = r;
    }
}

// ---------- prep: round weights to tf32, zero degree arrays -------------------
// NOTE: launched with coverage >= max(2*D_IN*D_HID, N_MID) threads so that the
// deg arrays are FULLY re-zeroed on EVERY call (R10 bug: 65536-thread launch
// left deg1[65536:100000] stale on the 2nd call -> scan overflow -> OOB write).
__global__ void prep_w(const float* __restrict__ Wl1, const float* __restrict__ Wr1,
                       const float* __restrict__ Wl2, const float* __restrict__ Wr2) {
    int i = blockIdx.x * blockDim.x + threadIdx.x;
    const int n1 = D_IN * D_HID;
    if (i < 2 * n1)
        g_W1[i] = tfr(i < n1 ? Wl1[i] : Wr1[i - n1]);
    const int n2 = D_HID * D_OUT;
    if (i < n2) {
        g_W2a[i] = tfr(Wl2[i]);
        g_W2b[i] = tfr(Wr2[i]);
    }
    if (i < N_MID) g_deg1[i] = 0;
    if (i < N_TGT) g_deg2[i] = 0;
}

// ---------------- CSR build: histogram / scan / place ------------------------
__global__ void hist_kernel(const int* __restrict__ tgt, int E, int* __restrict__ deg) {
    int i = blockIdx.x * blockDim.x + threadIdx.x;
    if (i < E) atomicAdd(deg + __ldg(tgt + i), 1);
}

__global__ void scan_block(const int* __restrict__ in, int n,
                           int* __restrict__ out_excl, int* __restrict__ sums) {
    __shared__ int sh[512];
    int gi = blockIdx.x * 512 + threadIdx.x;
    int v = gi < n ? in[gi] : 0;
    sh[threadIdx.x] = v;
    __syncthreads();
#pragma unroll
    for (int off = 1; off < 512; off <<= 1) {
        int t = threadIdx.x >= off ? sh[threadIdx.x - off] : 0;
        __syncthreads();
        sh[threadIdx.x] += t;
        __syncthreads();
    }
    if (gi < n) out_excl[gi] = sh[threadIdx.x] - v;   // exclusive
    if (threadIdx.x == 511) sums[blockIdx.x] = sh[511];
}

__global__ void scan_sums(int* __restrict__ sums, int nb) {
    __shared__ int sh[512];
    int v = (int)threadIdx.x < nb ? sums[threadIdx.x] : 0;
    sh[threadIdx.x] = v;
    __syncthreads();
#pragma unroll
    for (int off = 1; off < 512; off <<= 1) {
        int t = threadIdx.x >= off ? sh[threadIdx.x - off] : 0;
        __syncthreads();
        sh[threadIdx.x] += t;
        __syncthreads();
    }
    if ((int)threadIdx.x < nb) sums[threadIdx.x] = sh[threadIdx.x];  // inclusive
}

__global__ void scan_add(int* __restrict__ roff, int* __restrict__ woff,
                         const int* __restrict__ sums, int n) {
    int gi = blockIdx.x * 512 + threadIdx.x;
    if (gi >= n) return;
    int add = blockIdx.x > 0 ? __ldg(sums + blockIdx.x - 1) : 0;
    int r = roff[gi] + add;
    roff[gi] = r;
    woff[gi] = r;
}

__global__ void place_kernel(const int* __restrict__ src, const int* __restrict__ tgt,
                             int E, int* __restrict__ woff, int* __restrict__ sorted) {
    int i = blockIdx.x * blockDim.x + threadIdx.x;
    if (i >= E) return;
    int t = __ldg(tgt + i);
    int p = atomicAdd(woff + t, 1);
    sorted[p] = __ldg(src + i);
}

// ---------------- gather layer 1: warp per target, 2x16-lane groups ----------
// Accumulates fp16 rows of g_xh in fp32 regs, writes normalized tf32 agg1.
__global__ void gather1() {
    int w = (blockIdx.x * blockDim.x + threadIdx.x) >> 5;   // target id
    if (w >= N_MID) return;
    int lane = threadIdx.x & 31;
    int half = lane >> 4, l = lane & 15;
    int base = __ldg(g_roff1 + w);
    int deg  = __ldg(g_deg1 + w);
    float a0 = 0.f, a1 = 0.f, a2 = 0.f, a3 = 0.f,
          a4 = 0.f, a5 = 0.f, a6 = 0.f, a7 = 0.f;
    for (int j = half; j < deg; j += 2) {
        int s = __ldg(g_sorted1 + base + j);
        uint4 d = __ldg(reinterpret_cast<const uint4*>(g_xh + (size_t)s * D_IN) + l);
        const __half2* hp = reinterpret_cast<const __half2*>(&d);
        float2 f0 = __half22float2(hp[0]), f1 = __half22float2(hp[1]);
        float2 f2 = __half22float2(hp[2]), f3 = __half22float2(hp[3]);
        a0 += f0.x; a1 += f0.y; a2 += f1.x; a3 += f1.y;
        a4 += f2.x; a5 += f2.y; a6 += f3.x; a7 += f3.y;
    }
    a0 += __shfl_xor_sync(0xffffffffu, a0, 16);
    a1 += __shfl_xor_sync(0xffffffffu, a1, 16);
    a2 += __shfl_xor_sync(0xffffffffu, a2, 16);
    a3 += __shfl_xor_sync(0xffffffffu, a3, 16);
    a4 += __shfl_xor_sync(0xffffffffu, a4, 16);
    a5 += __shfl_xor_sync(0xffffffffu, a5, 16);
    a6 += __shfl_xor_sync(0xffffffffu, a6, 16);
    a7 += __shfl_xor_sync(0xffffffffu, a7, 16);
    if (half == 0) {
        float inv = 1.0f / (float)max(deg, 1);
        float* p = g_agg1 + (size_t)w * D_IN + l * 8;
        float4 v0, v1;
        v0.x = tfr(a0 * inv); v0.y = tfr(a1 * inv);
        v0.z = tfr(a2 * inv); v0.w = tfr(a3 * inv);
        v1.x = tfr(a4 * inv); v1.y = tfr(a5 * inv);
        v1.z = tfr(a6 * inv); v1.w = tfr(a7 * inv);
        *reinterpret_cast<float4*>(p)     = v0;
        *reinterpret_cast<float4*>(p + 4) = v1;
    }
}

// ---------------- gather layer 2: warp per target, 4x8-lane groups -----------
// Accumulates fp16 rows of g_hw, writes normalized fp32 agg2.
__global__ void gather2() {
    int w = (blockIdx.x * blockDim.x + threadIdx.x) >> 5;   // target id
    if (w >= N_TGT) return;
    int lane = threadIdx.x & 31;
    int q = lane >> 3, l = lane & 7;
    int base = __ldg(g_roff2 + w);
    int deg  = __ldg(g_deg2 + w);
    float a0 = 0.f, a1 = 0.f, a2 = 0.f, a3 = 0.f,
          a4 = 0.f, a5 = 0.f, a6 = 0.f, a7 = 0.f;
    for (int j = q; j < deg; j += 4) {
        int s = __ldg(g_sorted2 + base + j);
        uint4 d = __ldg(reinterpret_cast<const uint4*>(g_hw + (size_t)s * D_OUT) + l);
        const __half2* hp = reinterpret_cast<const __half2*>(&d);
        float2 f0 = __half22float2(hp[0]), f1 = __half22float2(hp[1]);
        float2 f2 = __half22float2(hp[2]), f3 = __half22float2(hp[3]);
        a0 += f0.x; a1 += f0.y; a2 += f1.x; a3 += f1.y;
        a4 += f2.x; a5 += f2.y; a6 += f3.x; a7 += f3.y;
    }
#pragma unroll
    for (int m = 8; m <= 16; m <<= 1) {
        a0 += __shfl_xor_sync(0xffffffffu, a0, m);
        a1 += __shfl_xor_sync(0xffffffffu, a1, m);
        a2 += __shfl_xor_sync(0xffffffffu, a2, m);
        a3 += __shfl_xor_sync(0xffffffffu, a3, m);
        a4 += __shfl_xor_sync(0xffffffffu, a4, m);
        a5 += __shfl_xor_sync(0xffffffffu, a5, m);
        a6 += __shfl_xor_sync(0xffffffffu, a6, m);
        a7 += __shfl_xor_sync(0xffffffffu, a7, m);
    }
    if (q == 0) {
        float inv = 1.0f / (float)max(deg, 1);
        float* p = g_agg2 + (size_t)w * D_OUT + l * 8;
        float4 v0, v1;
        v0.x = a0 * inv; v0.y = a1 * inv; v0.z = a2 * inv; v0.w = a3 * inv;
        v1.x = a4 * inv; v1.y = a5 * inv; v1.z = a6 * inv; v1.w = a7 * inv;
        *reinterpret_cast<float4*>(p)     = v0;
        *reinterpret_cast<float4*>(p + 4) = v1;
    }
}

// ---------------- tf32 tensor-core GEMM (operands pre-rounded to tf32) -------
// C[M,N] = [A0 | A1] @ B (+bias) (+ReLU), A0:[M,K1], A1:[M,K-K1], B:[K,N].
// EPI: 1 = tf32-rounded fp32 store, 2 = fp16 store, 3 = fp32 store + agg added.
__device__ __forceinline__ void mma_tf32(float* c, const uint32_t* a,
                                         const uint32_t* b) {
    asm volatile(
        "mma.sync.aligned.m16n8k8.row.col.f32.tf32.tf32.f32 "
        "{%0,%1,%2,%3}, {%4,%5,%6,%7}, {%8,%9}, {%0,%1,%2,%3};"
        : "+f"(c[0]), "+f"(c[1]), "+f"(c[2]), "+f"(c[3])
        : "r"(a[0]), "r"(a[1]), "r"(a[2]), "r"(a[3]), "r"(b[0]), "r"(b[1]));
}

template <int BM, int BN, int BK, int WM, int WN, bool RELU, int EPI, bool BIAS>
__global__ void __launch_bounds__(256, 1)
gemm_tf32(int M, int Nn, int K, int K1,
          const float* __restrict__ A0, const float* __restrict__ A1,
          const float* __restrict__ B, const float* __restrict__ bias,
          float* __restrict__ Cf, __half* __restrict__ Ch,
          const float* __restrict__ aggp) {
    constexpr int ASTR = BK + 4;   // ≡4 (mod 32): lanes (4g+t) conflict-free
    constexpr int BSTR = BN + 8;   // ≡8 (mod 32): lanes (8t+g) conflict-free
    constexpr int AS = BM * ASTR;
    constexpr int BS = BK * BSTR;
    constexpr int STAGE = AS + BS;
    constexpr int WARPS_M = BM / WM;
    constexpr int MT = WM / 16, NT = WN / 8;

    extern __shared__ float sm[];

    const int tid = threadIdx.x;
    const int warp = tid >> 5, lane = tid & 31;
    const int wm = warp % WARPS_M, wn = warp / WARPS_M;
    const int m0 = wm * WM, n0 = wn * WN;
    const int g = lane >> 2, t = lane & 3;
    const int row0 = blockIdx.y * BM, col0 = blockIdx.x * BN;
    const int K2s = K - K1;

    float acc[MT][NT][4];
#pragma unroll
    for (int i = 0; i < MT; i++)
#pragma unroll
        for (int j = 0; j < NT; j++)
#pragma unroll
            for (int r = 0; r < 4; r++) acc[i][j][r] = 0.f;

    auto load_stage = [&](int kt, int s) {
        float* As = sm + s * STAGE;
        float* Bs = As + AS;
        constexpr int A4 = BM * BK / 4;
#pragma unroll
        for (int p = 0; p < A4 / 256; p++) {
            int idx = tid + p * 256;
            int r = idx / (BK / 4);
            int kq = (idx % (BK / 4)) * 4;
            int gr = row0 + r;
            int cr = gr < M ? gr : M - 1;
            int gk = kt + kq;
            const float* src = (gk < K1)
                ? (A0 + (size_t)cr * K1 + gk)
                : (A1 + (size_t)cr * K2s + (gk - K1));
            uint32_t dst = (uint32_t)__cvta_generic_to_shared(As + r * ASTR + kq);
            int sz = gr < M ? 16 : 0;
            asm volatile("cp.async.cg.shared.global [%0], [%1], 16, %2;"
                         :: "r"(dst), "l"(src), "r"(sz));
        }
        constexpr int B4 = BK * BN / 4;
#pragma unroll
        for (int p = 0; p < B4 / 256; p++) {
            int idx = tid + p * 256;
            int kr = idx / (BN / 4);
            int nq = (idx % (BN / 4)) * 4;
            const float* src = B + (size_t)(kt + kr) * Nn + col0 + nq;
            uint32_t dst = (uint32_t)__cvta_generic_to_shared(Bs + kr * BSTR + nq);
            asm volatile("cp.async.cg.shared.global [%0], [%1], 16;"
                         :: "r"(dst), "l"(src));
        }
        asm volatile("cp.async.commit_group;");
    };

    auto compute = [&](int s) {
        const float* As = sm + s * STAGE;
        const float* Bs = As + AS;
#pragma unroll
        for (int ks = 0; ks < BK / 8; ks++) {
            const int k0 = ks * 8;
            uint32_t af[MT][4], bf[NT][2];
#pragma unroll
            for (int i = 0; i < MT; i++) {
                const float* a_lo = As + (m0 + 16 * i + g) * ASTR + k0;
                const float* a_hi = a_lo + 8 * ASTR;
                af[i][0] = __float_as_uint(a_lo[t]);
                af[i][1] = __float_as_uint(a_hi[t]);
                af[i][2] = __float_as_uint(a_lo[t + 4]);
                af[i][3] = __float_as_uint(a_hi[t + 4]);
            }
#pragma unroll
            for (int j = 0; j < NT; j++) {
                const float* bp = Bs + (k0 + t) * BSTR + n0 + 8 * j + g;
                bf[j][0] = __float_as_uint(bp[0]);
                bf[j][1] = __float_as_uint(bp[4 * BSTR]);
            }
#pragma unroll
            for (int i = 0; i < MT; i++)
#pragma unroll
                for (int j = 0; j < NT; j++)
                    mma_tf32(acc[i][j], af[i], bf[j]);
        }
    };

    load_stage(0, 0);
    const int NKT = K / BK;
    for (int kt = 1; kt < NKT; kt++) {
        load_stage(kt * BK, kt & 1);
        asm volatile("cp.async.wait_group 1;");
        __syncthreads();
        compute((kt - 1) & 1);
        __syncthreads();
    }
    asm volatile("cp.async.wait_group 0;");
    __syncthreads();
    compute((NKT - 1) & 1);

    // ---- epilogue ----
#pragma unroll
    for (int i = 0; i < MT; i++) {
        const int r1 = row0 + m0 + 16 * i + g;
        const int r2 = r1 + 8;
#pragma unroll
        for (int j = 0; j < NT; j++) {
            const int col = col0 + n0 + 8 * j + 2 * t;
            float2 bb = make_float2(0.f, 0.f);
            if (BIAS)
                bb = *reinterpret_cast<const float2*>(bias + col);
            float2 v0, v1;
            v0.x = acc[i][j][0] + bb.x; v0.y = acc[i][j][1] + bb.y;
            v1.x = acc[i][j][2] + bb.x; v1.y = acc[i][j][3] + bb.y;
            if (EPI == 3) {   // add pre-normalized agg
                if (r1 < M) {
                    float2 a = *reinterpret_cast<const float2*>(
                        aggp + (size_t)r1 * Nn + col);
                    v0.x += a.x; v0.y += a.y;
                }
                if (r2 < M) {
                    float2 a = *reinterpret_cast<const float2*>(
                        aggp + (size_t)r2 * Nn + col);
                    v1.x += a.x; v1.y += a.y;
                }
            }
            if (RELU) {
                v0.x = fmaxf(v0.x, 0.f); v0.y = fmaxf(v0.y, 0.f);
                v1.x = fmaxf(v1.x, 0.f); v1.y = fmaxf(v1.y, 0.f);
            }
            if (EPI == 1) {
                v0.x = tfr(v0.x); v0.y = tfr(v0.y);
                v1.x = tfr(v1.x); v1.y = tfr(v1.y);
            }
            if (EPI == 2) {
                if (r1 < M)
                    *reinterpret_cast<__half2*>(Ch + (size_t)r1 * Nn + col) =
                        __floats2half2_rn(v0.x, v0.y);
                if (r2 < M)
                    *reinterpret_cast<__half2*>(Ch + (size_t)r2 * Nn + col) =
                        __floats2half2_rn(v1.x, v1.y);
            } else {
                if (r1 < M)
                    *reinterpret_cast<float2*>(Cf + (size_t)r1 * Nn + col) = v0;
                if (r2 < M)
                    *reinterpret_cast<float2*>(Cf + (size_t)r2 * Nn + col) = v1;
            }
        }
    }
}

// ---------------- launch -----------------------------------------------------
extern "C" void kernel_launch(void* const* d_in, const int* in_sizes, int n_in,
                              void* d_out, int out_size) {
    const float* x   = (const float*)d_in[0];
    const int*   ei1 = (const int*)d_in[1];
    const int*   ei2 = (const int*)d_in[2];
    const float* Wl1 = (const float*)d_in[3];
    const float* Wr1 = (const float*)d_in[4];
    const float* b1  = (const float*)d_in[5];
    const float* Wl2 = (const float*)d_in[6];
    const float* Wr2 = (const float*)d_in[7];
    const float* b2  = (const float*)d_in[8];
    float* out = (float*)d_out;

    const int E1 = in_sizes[1] / 2;
    const int E2 = in_sizes[2] / 2;

    float *agg1, *h, *agg2, *xr, *W1, *W2a, *W2b;
    __half *hw;
    int *deg1, *roff1, *woff1, *sums1, *sorted1;
    int *deg2, *roff2, *woff2, *sums2, *sorted2;
    cudaGetSymbolAddress((void**)&agg1,    g_agg1);
    cudaGetSymbolAddress((void**)&h,       g_h);
    cudaGetSymbolAddress((void**)&agg2,    g_agg2);
    cudaGetSymbolAddress((void**)&xr,      g_xr);
    cudaGetSymbolAddress((void**)&W1,      g_W1);
    cudaGetSymbolAddress((void**)&W2a,     g_W2a);
    cudaGetSymbolAddress((void**)&W2b,     g_W2b);
    cudaGetSymbolAddress((void**)&hw,      g_hw);
    cudaGetSymbolAddress((void**)&deg1,    g_deg1);
    cudaGetSymbolAddress((void**)&roff1,   g_roff1);
    cudaGetSymbolAddress((void**)&woff1,   g_woff1);
    cudaGetSymbolAddress((void**)&sums1,   g_sums1);
    cudaGetSymbolAddress((void**)&sorted1, g_sorted1);
    cudaGetSymbolAddress((void**)&deg2,    g_deg2);
    cudaGetSymbolAddress((void**)&roff2,   g_roff2);
    cudaGetSymbolAddress((void**)&woff2,   g_woff2);
    cudaGetSymbolAddress((void**)&sums2,   g_sums2);
    cudaGetSymbolAddress((void**)&sorted2, g_sorted2);

    const int smem1 = 2 * (128 * 36 + 32 * 264) * (int)sizeof(float);
    cudaFuncSetAttribute(gemm_tf32<128, 256, 32, 64, 64, true, 1, true>,
                         cudaFuncAttributeMaxDynamicSharedMemorySize, smem1);
    const int smem2 = 2 * (128 * 36 + 32 * 72) * (int)sizeof(float);
    cudaFuncSetAttribute(gemm_tf32<128, 64, 32, 32, 32, false, 2, false>,
                         cudaFuncAttributeMaxDynamicSharedMemorySize, smem2);
    cudaFuncSetAttribute(gemm_tf32<128, 64, 32, 32, 32, false, 3, true>,
                         cudaFuncAttributeMaxDynamicSharedMemorySize, smem2);

    const int NB1 = (N_MID + 511) / 512;   // 196 scan blocks
    const int NB2 = (N_TGT + 511) / 512;   // 98

    // 1) prep  (prep_w coverage MUST span N_MID for deg re-zeroing every call)
    prep_x<<<(N_SRC * (D_IN / 4) + 255) / 256, 256>>>(x);
    {
        int cov = 2 * D_IN * D_HID;           // 65536
        if (cov < N_MID) cov = N_MID;         // 100000
        prep_w<<<(cov + 255) / 256, 256>>>(Wl1, Wr1, Wl2, Wr2);
    }

    // 2) CSR build, layer 1
    hist_kernel<<<(E1 + 255) / 256, 256>>>(ei1 + E1, E1, deg1);
    scan_block<<<NB1, 512>>>(deg1, N_MID, roff1, sums1);
    scan_sums<<<1, 512>>>(sums1, NB1);
    scan_add<<<NB1, 512>>>(roff1, woff1, sums1, N_MID);
    place_kernel<<<(E1 + 255) / 256, 256>>>(ei1, ei1 + E1, E1, woff1, sorted1);

    // 3) gather layer 1 -> agg1 (normalized + tf32-rounded)
    gather1<<<(N_MID * 32 + 255) / 256, 256>>>();

    // 4) h = relu([agg1 | xr] @ W1 + b1), stored tf32-rounded  [N_MID, 256]
    gemm_tf32<128, 256, 32, 64, 64, true, 1, true>
        <<<dim3(1, (N_MID + 127) / 128), 256, smem1>>>(
            N_MID, D_HID, 2 * D_IN, D_IN, agg1, xr, W1, b1, h, nullptr, nullptr);

    // 5) hW = h @ Wl2, stored fp16  [N_MID, 64]
    gemm_tf32<128, 64, 32, 32, 32, false, 2, false>
        <<<dim3(1, (N_MID + 127) / 128), 256, smem2>>>(
            N_MID, D_OUT, D_HID, D_HID, h, h, W2a, nullptr, nullptr, hw, nullptr);

    // 6) CSR build, layer 2
    hist_kernel<<<(E2 + 255) / 256, 256>>>(ei2 + E2, E2, deg2);
    scan_block<<<NB2, 512>>>(deg2, N_TGT, roff2, sums2);
    scan_sums<<<1, 512>>>(sums2, NB2);
    scan_add<<<NB2, 512>>>(roff2, woff2, sums2, N_TGT);
    place_kernel<<<(E2 + 255) / 256, 256>>>(ei2, ei2 + E2, E2, woff2, sorted2);

    // 7) gather layer 2 -> agg2 (normalized)
    gather2<<<(N_TGT * 32 + 255) / 256, 256>>>();

    // 8) out = h[:N_TGT] @ Wr2 + b2 + agg2   [N_TGT, 64]
    gemm_tf32<128, 64, 32, 32, 32, false, 3, true>
        <<<dim3(1, (N_TGT + 127) / 128), 256, smem2>>>(
            N_TGT, D_OUT, D_HID, D_HID, h, h, W2b, b2, out, nullptr, agg2);
}

// round 12
// speedup vs baseline: 2.9969x; 1.0734x over previous
#include <cuda_runtime.h>
#include <cuda_fp16.h>
#include <cstdint>

#define N_SRC 200000
#define N_MID 100000
#define N_TGT 50000
#define D_IN  128
#define D_HID 256
#define D_OUT 64
#define E1_MAX 1600000
#define E2_MAX 800000

// ---------------- scratch (device globals: no allocations allowed) ----------
__device__ __half g_xh[(size_t)N_SRC * D_IN];      // 51.2 MB fp16 copy of x
__device__ float  g_xr[(size_t)N_MID * D_IN];      // tf32-rounded x[:N_MID]
__device__ float  g_agg1[(size_t)N_MID * D_IN];    // normalized mean, tf32
__device__ float  g_h[(size_t)N_TGT * D_HID];      // tf32-rounded, rows < N_TGT only
__device__ __half g_hw[(size_t)N_MID * D_OUT];     // h @ Wl2 in fp16
__device__ float  g_agg2[(size_t)N_TGT * D_OUT];   // normalized mean
__device__ float  g_W1[2 * D_IN * D_HID];          // [Wl1;Wr1] tf32
__device__ __half g_W2ah[D_OUT * D_HID];           // Wl2 transposed [n][k], fp16
__device__ float  g_W2b[D_HID * D_OUT];            // Wr2 tf32
// CSR build scratch
__device__ int    g_deg1[N_MID],  g_roff1[N_MID],  g_woff1[N_MID];
__device__ int    g_deg2[N_TGT],  g_roff2[N_TGT],  g_woff2[N_TGT];
__device__ int    g_sums1[512],   g_sums2[512];
__device__ int    g_sorted1[E1_MAX], g_sorted2[E2_MAX];

__device__ __forceinline__ uint32_t f2tf(float x) {
    uint32_t r;
    asm("cvt.rna.tf32.f32 %0, %1;" : "=r"(r) : "f"(x));
    return r;
}
__device__ __forceinline__ float tfr(float x) { return __uint_as_float(f2tf(x)); }

// ---------------- prep: x -> fp16 copy + tf32 copy ---------------------------
__global__ void prep_x(const float* __restrict__ x) {
    int i = blockIdx.x * blockDim.x + threadIdx.x;   // float4 id
    if (i >= N_SRC * (D_IN / 4)) return;
    float4 v = reinterpret_cast<const float4*>(x)[i];
    reinterpret_cast<__half2*>(g_xh)[i * 2]     = __floats2half2_rn(v.x, v.y);
    reinterpret_cast<__half2*>(g_xh)[i * 2 + 1] = __floats2half2_rn(v.z, v.w);
    if (i < N_MID * (D_IN / 4)) {
        float4 r;
        r.x = tfr(v.x); r.y = tfr(v.y); r.z = tfr(v.z); r.w = tfr(v.w);
        reinterpret_cast<float4*>(g_xr)[i] = r;
    }
}

// ---------- prep: weights -> tf32/fp16, zero degree arrays --------------------
// Coverage MUST span max(2*D_IN*D_HID, N_MID) so deg arrays are fully re-zeroed
// on EVERY call (graph replays the same work; stale degrees -> scan overflow).
__global__ void prep_w(const float* __restrict__ Wl1, const float* __restrict__ Wr1,
                       const float* __restrict__ Wl2, const float* __restrict__ Wr2) {
    int i = blockIdx.x * blockDim.x + threadIdx.x;
    const int n1 = D_IN * D_HID;
    if (i < 2 * n1)
        g_W1[i] = tfr(i < n1 ? Wl1[i] : Wr1[i - n1]);
    const int n2 = D_HID * D_OUT;
    if (i < n2) {
        int k = i / D_OUT, n = i % D_OUT;
        g_W2ah[n * D_HID + k] = __float2half(Wl2[i]);   // transposed fp16
        g_W2b[i] = tfr(Wr2[i]);
    }
    if (i < N_MID) g_deg1[i] = 0;
    if (i < N_TGT) g_deg2[i] = 0;
}

// ---------------- CSR build: histogram / scan / place ------------------------
__global__ void hist_kernel(const int* __restrict__ tgt, int E, int* __restrict__ deg) {
    int i = blockIdx.x * blockDim.x + threadIdx.x;
    if (i < E) atomicAdd(deg + __ldg(tgt + i), 1);
}

__global__ void scan_block(const int* __restrict__ in, int n,
                           int* __restrict__ out_excl, int* __restrict__ sums) {
    __shared__ int sh[512];
    int gi = blockIdx.x * 512 + threadIdx.x;
    int v = gi < n ? in[gi] : 0;
    sh[threadIdx.x] = v;
    __syncthreads();
#pragma unroll
    for (int off = 1; off < 512; off <<= 1) {
        int t = threadIdx.x >= off ? sh[threadIdx.x - off] : 0;
        __syncthreads();
        sh[threadIdx.x] += t;
        __syncthreads();
    }
    if (gi < n) out_excl[gi] = sh[threadIdx.x] - v;   // exclusive
    if (threadIdx.x == 511) sums[blockIdx.x] = sh[511];
}

__global__ void scan_sums(int* __restrict__ sums, int nb) {
    __shared__ int sh[512];
    int v = (int)threadIdx.x < nb ? sums[threadIdx.x] : 0;
    sh[threadIdx.x] = v;
    __syncthreads();
#pragma unroll
    for (int off = 1; off < 512; off <<= 1) {
        int t = threadIdx.x >= off ? sh[threadIdx.x - off] : 0;
        __syncthreads();
        sh[threadIdx.x] += t;
        __syncthreads();
    }
    if ((int)threadIdx.x < nb) sums[threadIdx.x] = sh[threadIdx.x];  // inclusive
}

__global__ void scan_add(int* __restrict__ roff, int* __restrict__ woff,
                         const int* __restrict__ sums, int n) {
    int gi = blockIdx.x * 512 + threadIdx.x;
    if (gi >= n) return;
    int add = blockIdx.x > 0 ? __ldg(sums + blockIdx.x - 1) : 0;
    int r = roff[gi] + add;
    roff[gi] = r;
    woff[gi] = r;
}

__global__ void place_kernel(const int* __restrict__ src, const int* __restrict__ tgt,
                             int E, int* __restrict__ woff, int* __restrict__ sorted) {
    int i = blockIdx.x * blockDim.x + threadIdx.x;
    if (i >= E) return;
    int t = __ldg(tgt + i);
    int p = atomicAdd(woff + t, 1);
    sorted[p] = __ldg(src + i);
}

// ---------------- gather layer 1: warp per target, 2x16-lane groups ----------
__global__ void gather1() {
    int w = (blockIdx.x * blockDim.x + threadIdx.x) >> 5;   // target id
    if (w >= N_MID) return;
    int lane = threadIdx.x & 31;
    int half = lane >> 4, l = lane & 15;
    int base = __ldg(g_roff1 + w);
    int deg  = __ldg(g_deg1 + w);
    float a0 = 0.f, a1 = 0.f, a2 = 0.f, a3 = 0.f,
          a4 = 0.f, a5 = 0.f, a6 = 0.f, a7 = 0.f;
    for (int j = half; j < deg; j += 2) {
        int s = __ldg(g_sorted1 + base + j);
        uint4 d = __ldg(reinterpret_cast<const uint4*>(g_xh + (size_t)s * D_IN) + l);
        const __half2* hp = reinterpret_cast<const __half2*>(&d);
        float2 f0 = __half22float2(hp[0]), f1 = __half22float2(hp[1]);
        float2 f2 = __half22float2(hp[2]), f3 = __half22float2(hp[3]);
        a0 += f0.x; a1 += f0.y; a2 += f1.x; a3 += f1.y;
        a4 += f2.x; a5 += f2.y; a6 += f3.x; a7 += f3.y;
    }
    a0 += __shfl_xor_sync(0xffffffffu, a0, 16);
    a1 += __shfl_xor_sync(0xffffffffu, a1, 16);
    a2 += __shfl_xor_sync(0xffffffffu, a2, 16);
    a3 += __shfl_xor_sync(0xffffffffu, a3, 16);
    a4 += __shfl_xor_sync(0xffffffffu, a4, 16);
    a5 += __shfl_xor_sync(0xffffffffu, a5, 16);
    a6 += __shfl_xor_sync(0xffffffffu, a6, 16);
    a7 += __shfl_xor_sync(0xffffffffu, a7, 16);
    if (half == 0) {
        float inv = 1.0f / (float)max(deg, 1);
        float* p = g_agg1 + (size_t)w * D_IN + l * 8;
        float4 v0, v1;
        v0.x = tfr(a0 * inv); v0.y = tfr(a1 * inv);
        v0.z = tfr(a2 * inv); v0.w = tfr(a3 * inv);
        v1.x = tfr(a4 * inv); v1.y = tfr(a5 * inv);
        v1.z = tfr(a6 * inv); v1.w = tfr(a7 * inv);
        *reinterpret_cast<float4*>(p)     = v0;
        *reinterpret_cast<float4*>(p + 4) = v1;
    }
}

// ---------------- gather layer 2: warp per target, 4x8-lane groups -----------
__global__ void gather2() {
    int w = (blockIdx.x * blockDim.x + threadIdx.x) >> 5;   // target id
    if (w >= N_TGT) return;
    int lane = threadIdx.x & 31;
    int q = lane >> 3, l = lane & 7;
    int base = __ldg(g_roff2 + w);
    int deg  = __ldg(g_deg2 + w);
    float a0 = 0.f, a1 = 0.f, a2 = 0.f, a3 = 0.f,
          a4 = 0.f, a5 = 0.f, a6 = 0.f, a7 = 0.f;
    for (int j = q; j < deg; j += 4) {
        int s = __ldg(g_sorted2 + base + j);
        uint4 d = __ldg(reinterpret_cast<const uint4*>(g_hw + (size_t)s * D_OUT) + l);
        const __half2* hp = reinterpret_cast<const __half2*>(&d);
        float2 f0 = __half22float2(hp[0]), f1 = __half22float2(hp[1]);
        float2 f2 = __half22float2(hp[2]), f3 = __half22float2(hp[3]);
        a0 += f0.x; a1 += f0.y; a2 += f1.x; a3 += f1.y;
        a4 += f2.x; a5 += f2.y; a6 += f3.x; a7 += f3.y;
    }
#pragma unroll
    for (int m = 8; m <= 16; m <<= 1) {
        a0 += __shfl_xor_sync(0xffffffffu, a0, m);
        a1 += __shfl_xor_sync(0xffffffffu, a1, m);
        a2 += __shfl_xor_sync(0xffffffffu, a2, m);
        a3 += __shfl_xor_sync(0xffffffffu, a3, m);
        a4 += __shfl_xor_sync(0xffffffffu, a4, m);
        a5 += __shfl_xor_sync(0xffffffffu, a5, m);
        a6 += __shfl_xor_sync(0xffffffffu, a6, m);
        a7 += __shfl_xor_sync(0xffffffffu, a7, m);
    }
    if (q == 0) {
        float inv = 1.0f / (float)max(deg, 1);
        float* p = g_agg2 + (size_t)w * D_OUT + l * 8;
        float4 v0, v1;
        v0.x = a0 * inv; v0.y = a1 * inv; v0.z = a2 * inv; v0.w = a3 * inv;
        v1.x = a4 * inv; v1.y = a5 * inv; v1.z = a6 * inv; v1.w = a7 * inv;
        *reinterpret_cast<float4*>(p)     = v0;
        *reinterpret_cast<float4*>(p + 4) = v1;
    }
}

// ---------------- tf32 tensor-core GEMM --------------------------------------
// C[M,N] = [A0 | A1] @ B (+bias) (+ReLU).
// EPI 1: tf32-rounded fp32 store, rows < store_lim only.
// EPI 3: fp32 store + pre-normalized agg added.
// FUSE:  additionally compute hw = h_tile @ W2a (fp16 MMA) in the epilogue.
__device__ __forceinline__ void mma_tf32(float* c, const uint32_t* a,
                                         const uint32_t* b) {
    asm volatile(
        "mma.sync.aligned.m16n8k8.row.col.f32.tf32.tf32.f32 "
        "{%0,%1,%2,%3}, {%4,%5,%6,%7}, {%8,%9}, {%0,%1,%2,%3};"
        : "+f"(c[0]), "+f"(c[1]), "+f"(c[2]), "+f"(c[3])
        : "r"(a[0]), "r"(a[1]), "r"(a[2]), "r"(a[3]), "r"(b[0]), "r"(b[1]));
}

__device__ __forceinline__ void mma_f16(float* c, const uint32_t* a,
                                        const uint32_t* b) {
    asm volatile(
        "mma.sync.aligned.m16n8k16.row.col.f32.f16.f16.f32 "
        "{%0,%1,%2,%3}, {%4,%5,%6,%7}, {%8,%9}, {%0,%1,%2,%3};"
        : "+f"(c[0]), "+f"(c[1]), "+f"(c[2]), "+f"(c[3])
        : "r"(a[0]), "r"(a[1]), "r"(a[2]), "r"(a[3]), "r"(b[0]), "r"(b[1]));
}

template <int BM, int BN, int BK, int WM, int WN, bool RELU, int EPI, bool BIAS,
          bool FUSE>
__global__ void __launch_bounds__(256, 1)
gemm_tf32(int M, int Nn, int K, int K1,
          const float* __restrict__ A0, const float* __restrict__ A1,
          const float* __restrict__ B, const float* __restrict__ bias,
          float* __restrict__ Cf, const float* __restrict__ aggp,
          __half* __restrict__ hwp, const __half* __restrict__ w2h,
          int store_lim) {
    constexpr int ASTR = BK + 4;   // ≡4 (mod 32): lanes (4g+t) conflict-free
    constexpr int BSTR = BN + 8;   // ≡8 (mod 32): lanes (8t+g) conflict-free
    constexpr int AS = BM * ASTR;
    constexpr int BS = BK * BSTR;
    constexpr int STAGE = AS + BS;
    constexpr int WARPS_M = BM / WM;
    constexpr int MT = WM / 16, NT = WN / 8;

    extern __shared__ float sm[];

    const int tid = threadIdx.x;
    const int warp = tid >> 5, lane = tid & 31;
    const int wm = warp % WARPS_M, wn = warp / WARPS_M;
    const int m0 = wm * WM, n0 = wn * WN;
    const int g = lane >> 2, t = lane & 3;
    const int row0 = blockIdx.y * BM, col0 = blockIdx.x * BN;
    const int K2s = K - K1;

    float acc[MT][NT][4];
#pragma unroll
    for (int i = 0; i < MT; i++)
#pragma unroll
        for (int j = 0; j < NT; j++)
#pragma unroll
            for (int r = 0; r < 4; r++) acc[i][j][r] = 0.f;

    auto load_stage = [&](int kt, int s) {
        float* As = sm + s * STAGE;
        float* Bs = As + AS;
        constexpr int A4 = BM * BK / 4;
#pragma unroll
        for (int p = 0; p < A4 / 256; p++) {
            int idx = tid + p * 256;
            int r = idx / (BK / 4);
            int kq = (idx % (BK / 4)) * 4;
            int gr = row0 + r;
            int cr = gr < M ? gr : M - 1;
            int gk = kt + kq;
            const float* src = (gk < K1)
                ? (A0 + (size_t)cr * K1 + gk)
                : (A1 + (size_t)cr * K2s + (gk - K1));
            uint32_t dst = (uint32_t)__cvta_generic_to_shared(As + r * ASTR + kq);
            int sz = gr < M ? 16 : 0;
            asm volatile("cp.async.cg.shared.global [%0], [%1], 16, %2;"
                         :: "r"(dst), "l"(src), "r"(sz));
        }
        constexpr int B4 = BK * BN / 4;
#pragma unroll
        for (int p = 0; p < B4 / 256; p++) {
            int idx = tid + p * 256;
            int kr = idx / (BN / 4);
            int nq = (idx % (BN / 4)) * 4;
            const float* src = B + (size_t)(kt + kr) * Nn + col0 + nq;
            uint32_t dst = (uint32_t)__cvta_generic_to_shared(Bs + kr * BSTR + nq);
            asm volatile("cp.async.cg.shared.global [%0], [%1], 16;"
                         :: "r"(dst), "l"(src));
        }
        asm volatile("cp.async.commit_group;");
    };

    auto compute = [&](int s) {
        const float* As = sm + s * STAGE;
        const float* Bs = As + AS;
#pragma unroll
        for (int ks = 0; ks < BK / 8; ks++) {
            const int k0 = ks * 8;
            uint32_t af[MT][4], bf[NT][2];
#pragma unroll
            for (int i = 0; i < MT; i++) {
                const float* a_lo = As + (m0 + 16 * i + g) * ASTR + k0;
                const float* a_hi = a_lo + 8 * ASTR;
                af[i][0] = __float_as_uint(a_lo[t]);
                af[i][1] = __float_as_uint(a_hi[t]);
                af[i][2] = __float_as_uint(a_lo[t + 4]);
                af[i][3] = __float_as_uint(a_hi[t + 4]);
            }
#pragma unroll
            for (int j = 0; j < NT; j++) {
                const float* bp = Bs + (k0 + t) * BSTR + n0 + 8 * j + g;
                bf[j][0] = __float_as_uint(bp[0]);
                bf[j][1] = __float_as_uint(bp[4 * BSTR]);
            }
#pragma unroll
            for (int i = 0; i < MT; i++)
#pragma unroll
                for (int j = 0; j < NT; j++)
                    mma_tf32(acc[i][j], af[i], bf[j]);
        }
    };

    load_stage(0, 0);
    const int NKT = K / BK;
    for (int kt = 1; kt < NKT; kt++) {
        load_stage(kt * BK, kt & 1);
        asm volatile("cp.async.wait_group 1;");
        __syncthreads();
        compute((kt - 1) & 1);
        __syncthreads();
    }
    asm volatile("cp.async.wait_group 0;");
    __syncthreads();
    compute((NKT - 1) & 1);

    // ---- fused-epilogue smem (aliases the dead stage buffers) ----
    constexpr int HSTR = 264;   // halves; 264%64==8 -> banks (4g+t) bijective
    constexpr int WSTR = 264;
    __half* Hs  = reinterpret_cast<__half*>(sm);
    __half* W2s = Hs + BM * HSTR;                 // 67584 + 33792 B <= smem1

    if constexpr (FUSE) __syncthreads();          // stage smem reads done

    // ---- epilogue: bias (+ReLU) (+tf32 round), stores ----
#pragma unroll
    for (int i = 0; i < MT; i++) {
        const int r1 = row0 + m0 + 16 * i + g;
        const int r2 = r1 + 8;
#pragma unroll
        for (int j = 0; j < NT; j++) {
            const int col = col0 + n0 + 8 * j + 2 * t;
            float2 bb = make_float2(0.f, 0.f);
            if (BIAS)
                bb = *reinterpret_cast<const float2*>(bias + col);
            float2 v0, v1;
            v0.x = acc[i][j][0] + bb.x; v0.y = acc[i][j][1] + bb.y;
            v1.x = acc[i][j][2] + bb.x; v1.y = acc[i][j][3] + bb.y;
            if (EPI == 3) {   // add pre-normalized agg
                if (r1 < M) {
                    float2 a = *reinterpret_cast<const float2*>(
                        aggp + (size_t)r1 * Nn + col);
                    v0.x += a.x; v0.y += a.y;
                }
                if (r2 < M) {
                    float2 a = *reinterpret_cast<const float2*>(
                        aggp + (size_t)r2 * Nn + col);
                    v1.x += a.x; v1.y += a.y;
                }
            }
            if (RELU) {
                v0.x = fmaxf(v0.x, 0.f); v0.y = fmaxf(v0.y, 0.f);
                v1.x = fmaxf(v1.x, 0.f); v1.y = fmaxf(v1.y, 0.f);
            }
            if (EPI == 1) {
                v0.x = tfr(v0.x); v0.y = tfr(v0.y);
                v1.x = tfr(v1.x); v1.y = tfr(v1.y);
                if (r1 < store_lim)
                    *reinterpret_cast<float2*>(Cf + (size_t)r1 * Nn + col) = v0;
                if (r2 < store_lim)
                    *reinterpret_cast<float2*>(Cf + (size_t)r2 * Nn + col) = v1;
            } else {
                if (r1 < M)
                    *reinterpret_cast<float2*>(Cf + (size_t)r1 * Nn + col) = v0;
                if (r2 < M)
                    *reinterpret_cast<float2*>(Cf + (size_t)r2 * Nn + col) = v1;
            }
            if constexpr (FUSE) {   // stash h tile in smem as fp16
                const int lr = m0 + 16 * i + g, lc = n0 + 8 * j + 2 * t;
                *reinterpret_cast<__half2*>(Hs + lr * HSTR + lc) =
                    __floats2half2_rn(v0.x, v0.y);
                *reinterpret_cast<__half2*>(Hs + (lr + 8) * HSTR + lc) =
                    __floats2half2_rn(v1.x, v1.y);
            }
        }
    }

    if constexpr (FUSE) {
        // load W2a fp16 ([64][256] n-major) into W2s with pad
        const uint4* wsrc = reinterpret_cast<const uint4*>(w2h);
        for (int p = tid; p < (D_OUT * D_HID) / 8; p += 256) {
            int n = p >> 5;                 // 32 uint4 per 256-half row
            int kq = (p & 31) * 8;
            uint4 v = __ldg(wsrc + p);
            *reinterpret_cast<uint4*>(W2s + n * WSTR + kq) = v;
        }
        __syncthreads();

        // second GEMM: hw[128][64] = Hs[128][256] @ W2s^T, fp16 MMA m16n8k16
        const int m2 = (warp & 3) * 32;     // 4 warps along M
        const int n2 = (warp >> 2) * 32;    // 2 warps along N
        float hwacc[2][4][4];
#pragma unroll
        for (int i = 0; i < 2; i++)
#pragma unroll
            for (int j = 0; j < 4; j++)
#pragma unroll
                for (int r = 0; r < 4; r++) hwacc[i][j][r] = 0.f;

#pragma unroll
        for (int kk = 0; kk < D_HID; kk += 16) {
            uint32_t ha[2][4], hb[4][2];
#pragma unroll
            for (int i = 0; i < 2; i++) {
                const __half* b0 = Hs + (m2 + 16 * i + g) * HSTR + kk + 2 * t;
                const __half* b1 = b0 + 8 * HSTR;
                ha[i][0] = *reinterpret_cast<const uint32_t*>(b0);
                ha[i][1] = *reinterpret_cast<const uint32_t*>(b1);
                ha[i][2] = *reinterpret_cast<const uint32_t*>(b0 + 8);
                ha[i][3] = *reinterpret_cast<const uint32_t*>(b1 + 8);
            }
#pragma unroll
            for (int j = 0; j < 4; j++) {
                const __half* bp = W2s + (n2 + 8 * j + g) * WSTR + kk + 2 * t;
                hb[j][0] = *reinterpret_cast<const uint32_t*>(bp);
                hb[j][1] = *reinterpret_cast<const uint32_t*>(bp + 8);
            }
#pragma unroll
            for (int i = 0; i < 2; i++)
#pragma unroll
                for (int j = 0; j < 4; j++)
                    mma_f16(hwacc[i][j], ha[i], hb[j]);
        }

#pragma unroll
        for (int i = 0; i < 2; i++) {
            const int r1 = row0 + m2 + 16 * i + g;
            const int r2 = r1 + 8;
#pragma unroll
            for (int j = 0; j < 4; j++) {
                const int col = n2 + 8 * j + 2 * t;
                if (r1 < M)
                    *reinterpret_cast<__half2*>(hwp + (size_t)r1 * D_OUT + col) =
                        __floats2half2_rn(hwacc[i][j][0], hwacc[i][j][1]);
                if (r2 < M)
                    *reinterpret_cast<__half2*>(hwp + (size_t)r2 * D_OUT + col) =
                        __floats2half2_rn(hwacc[i][j][2], hwacc[i][j][3]);
            }
        }
    }
}

// ---------------- launch -----------------------------------------------------
extern "C" void kernel_launch(void* const* d_in, const int* in_sizes, int n_in,
                              void* d_out, int out_size) {
    const float* x   = (const float*)d_in[0];
    const int*   ei1 = (const int*)d_in[1];
    const int*   ei2 = (const int*)d_in[2];
    const float* Wl1 = (const float*)d_in[3];
    const float* Wr1 = (const float*)d_in[4];
    const float* b1  = (const float*)d_in[5];
    const float* Wl2 = (const float*)d_in[6];
    const float* Wr2 = (const float*)d_in[7];
    const float* b2  = (const float*)d_in[8];
    float* out = (float*)d_out;

    const int E1 = in_sizes[1] / 2;
    const int E2 = in_sizes[2] / 2;

    float *agg1, *h, *agg2, *xr, *W1, *W2b;
    __half *hw, *w2ah;
    int *deg1, *roff1, *woff1, *sums1, *sorted1;
    int *deg2, *roff2, *woff2, *sums2, *sorted2;
    cudaGetSymbolAddress((void**)&agg1,    g_agg1);
    cudaGetSymbolAddress((void**)&h,       g_h);
    cudaGetSymbolAddress((void**)&agg2,    g_agg2);
    cudaGetSymbolAddress((void**)&xr,      g_xr);
    cudaGetSymbolAddress((void**)&W1,      g_W1);
    cudaGetSymbolAddress((void**)&W2b,     g_W2b);
    cudaGetSymbolAddress((void**)&hw,      g_hw);
    cudaGetSymbolAddress((void**)&w2ah,    g_W2ah);
    cudaGetSymbolAddress((void**)&deg1,    g_deg1);
    cudaGetSymbolAddress((void**)&roff1,   g_roff1);
    cudaGetSymbolAddress((void**)&woff1,   g_woff1);
    cudaGetSymbolAddress((void**)&sums1,   g_sums1);
    cudaGetSymbolAddress((void**)&sorted1, g_sorted1);
    cudaGetSymbolAddress((void**)&deg2,    g_deg2);
    cudaGetSymbolAddress((void**)&roff2,   g_roff2);
    cudaGetSymbolAddress((void**)&woff2,   g_woff2);
    cudaGetSymbolAddress((void**)&sums2,   g_sums2);
    cudaGetSymbolAddress((void**)&sorted2, g_sorted2);

    // GEMM1 fused: 2 stages (104448 B) >= fused epilogue (101376 B)
    const int smem1 = 2 * (128 * 36 + 32 * 264) * (int)sizeof(float);
    cudaFuncSetAttribute(gemm_tf32<128, 256, 32, 64, 64, true, 1, true, true>,
                         cudaFuncAttributeMaxDynamicSharedMemorySize, smem1);
    const int smem2 = 2 * (128 * 36 + 32 * 72) * (int)sizeof(float);
    cudaFuncSetAttribute(gemm_tf32<128, 64, 32, 32, 32, false, 3, true, false>,
                         cudaFuncAttributeMaxDynamicSharedMemorySize, smem2);

    const int NB1 = (N_MID + 511) / 512;
    const int NB2 = (N_TGT + 511) / 512;

    // 1) prep  (prep_w coverage spans N_MID for deg re-zeroing every call)
    prep_x<<<(N_SRC * (D_IN / 4) + 255) / 256, 256>>>(x);
    {
        int cov = 2 * D_IN * D_HID;           // 65536
        if (cov < N_MID) cov = N_MID;         // 100000
        prep_w<<<(cov + 255) / 256, 256>>>(Wl1, Wr1, Wl2, Wr2);
    }

    // 2) CSR build, layer 1
    hist_kernel<<<(E1 + 255) / 256, 256>>>(ei1 + E1, E1, deg1);
    scan_block<<<NB1, 512>>>(deg1, N_MID, roff1, sums1);
    scan_sums<<<1, 512>>>(sums1, NB1);
    scan_add<<<NB1, 512>>>(roff1, woff1, sums1, N_MID);
    place_kernel<<<(E1 + 255) / 256, 256>>>(ei1, ei1 + E1, E1, woff1, sorted1);

    // 3) gather layer 1 -> agg1 (normalized + tf32-rounded)
    gather1<<<(N_MID * 32 + 255) / 256, 256>>>();

    // 4) h = relu([agg1 | xr] @ W1 + b1)  [N_MID, 256]
    //    fused: h[:N_TGT] stored fp32; hw = h @ Wl2 stored fp16 for ALL rows
    gemm_tf32<128, 256, 32, 64, 64, true, 1, true, true>
        <<<dim3(1, (N_MID + 127) / 128), 256, smem1>>>(
            N_MID, D_HID, 2 * D_IN, D_IN, agg1, xr, W1, b1, h, nullptr,
            hw, w2ah, N_TGT);

    // 5) CSR build, layer 2
    hist_kernel<<<(E2 + 255) / 256, 256>>>(ei2 + E2, E2, deg2);
    scan_block<<<NB2, 512>>>(deg2, N_TGT, roff2, sums2);
    scan_sums<<<1, 512>>>(sums2, NB2);
    scan_add<<<NB2, 512>>>(roff2, woff2, sums2, N_TGT);
    place_kernel<<<(E2 + 255) / 256, 256>>>(ei2, ei2 + E2, E2, woff2, sorted2);

    // 6) gather layer 2 -> agg2 (normalized)
    gather2<<<(N_TGT * 32 + 255) / 256, 256>>>();

    // 7) out = h[:N_TGT] @ Wr2 + b2 + agg2   [N_TGT, 64]
    gemm_tf32<128, 64, 32, 32, 32, false, 3, true, false>
        <<<dim3(1, (N_TGT + 127) / 128), 256, smem2>>>(
            N_TGT, D_OUT, D_HID, D_HID, h, h, W2b, b2, out, agg2,
            nullptr, nullptr, 0);
}

// round 14
// speedup vs baseline: 3.6140x; 1.2059x over previous
#include <cuda_runtime.h>
#include <cuda_fp16.h>
#include <cstdint>

#define N_SRC 200000
#define N_MID 100000
#define N_TGT 50000
#define D_IN  128
#define D_HID 256
#define D_OUT 64
#define E1_MAX 1600000
#define E2_MAX 800000

// ---------------- scratch (device globals: no allocations allowed) ----------
__device__ __half g_xh[(size_t)N_SRC * D_IN];      // 51.2 MB fp16 copy of x
__device__ __half g_agg1[(size_t)N_MID * D_IN];    // normalized mean, fp16
__device__ __half g_h[(size_t)N_TGT * D_HID];      // fp16, rows < N_TGT only
__device__ __half g_hw[(size_t)N_MID * D_OUT];     // h @ Wl2 in fp16
__device__ float  g_agg2[(size_t)N_TGT * D_OUT];   // normalized mean
__device__ __half g_W1h[D_HID * (2 * D_IN)];       // [Wl1;Wr1] transposed [n][k] fp16
__device__ __half g_W2ah[D_OUT * D_HID];           // Wl2 transposed [n][k] fp16
__device__ __half g_W2bh[D_OUT * D_HID];           // Wr2 transposed [n][k] fp16
// CSR build scratch
__device__ int    g_deg1[N_MID],  g_roff1[N_MID],  g_woff1[N_MID];
__device__ int    g_deg2[N_TGT],  g_roff2[N_TGT],  g_woff2[N_TGT];
__device__ int    g_sums1[512],   g_sums2[512];
__device__ int    g_sorted1[E1_MAX], g_sorted2[E2_MAX];

// ---------------- prep: x -> fp16 copy ---------------------------------------
__global__ void prep_x(const float* __restrict__ x) {
    int i = blockIdx.x * blockDim.x + threadIdx.x;   // float4 id
    if (i >= N_SRC * (D_IN / 4)) return;
    float4 v = reinterpret_cast<const float4*>(x)[i];
    reinterpret_cast<__half2*>(g_xh)[i * 2]     = __floats2half2_rn(v.x, v.y);
    reinterpret_cast<__half2*>(g_xh)[i * 2 + 1] = __floats2half2_rn(v.z, v.w);
}

// ---------- prep: weights -> fp16 transposed, zero degree arrays --------------
// Coverage MUST span max(2*D_IN*D_HID, N_MID) so deg arrays are fully re-zeroed
// on EVERY call (graph replays the same work; stale degrees -> scan overflow).
__global__ void prep_w(const float* __restrict__ Wl1, const float* __restrict__ Wr1,
                       const float* __restrict__ Wl2, const float* __restrict__ Wr2) {
    int i = blockIdx.x * blockDim.x + threadIdx.x;
    if (i < 2 * D_IN * D_HID) {            // 65536: W1 [k=256][n=256] -> [n][k]
        int k = i >> 8, n = i & 255;
        float v = (k < D_IN) ? Wl1[k * D_HID + n] : Wr1[(k - D_IN) * D_HID + n];
        g_W1h[n * (2 * D_IN) + k] = __float2half(v);
    }
    if (i < D_HID * D_OUT) {               // 16384: W2 [k=256][n=64] -> [n][k]
        int k = i >> 6, n = i & 63;
        g_W2ah[n * D_HID + k] = __float2half(Wl2[k * D_OUT + n]);
        g_W2bh[n * D_HID + k] = __float2half(Wr2[k * D_OUT + n]);
    }
    if (i < N_MID) g_deg1[i] = 0;
    if (i < N_TGT) g_deg2[i] = 0;
}

// ---------------- CSR build: histogram / scan / place ------------------------
__global__ void hist_kernel(const int* __restrict__ tgt, int E, int* __restrict__ deg) {
    int i = blockIdx.x * blockDim.x + threadIdx.x;
    if (i < E) atomicAdd(deg + __ldg(tgt + i), 1);
}

__global__ void scan_block(const int* __restrict__ in, int n,
                           int* __restrict__ out_excl, int* __restrict__ sums) {
    __shared__ int sh[512];
    int gi = blockIdx.x * 512 + threadIdx.x;
    int v = gi < n ? in[gi] : 0;
    sh[threadIdx.x] = v;
    __syncthreads();
#pragma unroll
    for (int off = 1; off < 512; off <<= 1) {
        int t = threadIdx.x >= off ? sh[threadIdx.x - off] : 0;
        __syncthreads();
        sh[threadIdx.x] += t;
        __syncthreads();
    }
    if (gi < n) out_excl[gi] = sh[threadIdx.x] - v;   // exclusive
    if (threadIdx.x == 511) sums[blockIdx.x] = sh[511];
}

__global__ void scan_sums(int* __restrict__ sums, int nb) {
    __shared__ int sh[512];
    int v = (int)threadIdx.x < nb ? sums[threadIdx.x] : 0;
    sh[threadIdx.x] = v;
    __syncthreads();
#pragma unroll
    for (int off = 1; off < 512; off <<= 1) {
        int t = threadIdx.x >= off ? sh[threadIdx.x - off] : 0;
        __syncthreads();
        sh[threadIdx.x] += t;
        __syncthreads();
    }
    if ((int)threadIdx.x < nb) sums[threadIdx.x] = sh[threadIdx.x];  // inclusive
}

__global__ void scan_add(int* __restrict__ roff, int* __restrict__ woff,
                         const int* __restrict__ sums, int n) {
    int gi = blockIdx.x * 512 + threadIdx.x;
    if (gi >= n) return;
    int add = blockIdx.x > 0 ? __ldg(sums + blockIdx.x - 1) : 0;
    int r = roff[gi] + add;
    roff[gi] = r;
    woff[gi] = r;
}

__global__ void place_kernel(const int* __restrict__ src, const int* __restrict__ tgt,
                             int E, int* __restrict__ woff, int* __restrict__ sorted) {
    int i = blockIdx.x * blockDim.x + threadIdx.x;
    if (i >= E) return;
    int t = __ldg(tgt + i);
    int p = atomicAdd(woff + t, 1);
    sorted[p] = __ldg(src + i);
}

// ---------------- gather layer 1: warp per target, 2x16-lane groups ----------
// Accumulates fp16 rows of g_xh in fp32 regs, writes normalized fp16 agg1.
__global__ void gather1() {
    int w = (blockIdx.x * blockDim.x + threadIdx.x) >> 5;   // target id
    if (w >= N_MID) return;
    int lane = threadIdx.x & 31;
    int half = lane >> 4, l = lane & 15;
    int base = __ldg(g_roff1 + w);
    int deg  = __ldg(g_deg1 + w);
    float a0 = 0.f, a1 = 0.f, a2 = 0.f, a3 = 0.f,
          a4 = 0.f, a5 = 0.f, a6 = 0.f, a7 = 0.f;
    for (int j = half; j < deg; j += 2) {
        int s = __ldg(g_sorted1 + base + j);
        uint4 d = __ldg(reinterpret_cast<const uint4*>(g_xh + (size_t)s * D_IN) + l);
        const __half2* hp = reinterpret_cast<const __half2*>(&d);
        float2 f0 = __half22float2(hp[0]), f1 = __half22float2(hp[1]);
        float2 f2 = __half22float2(hp[2]), f3 = __half22float2(hp[3]);
        a0 += f0.x; a1 += f0.y; a2 += f1.x; a3 += f1.y;
        a4 += f2.x; a5 += f2.y; a6 += f3.x; a7 += f3.y;
    }
    a0 += __shfl_xor_sync(0xffffffffu, a0, 16);
    a1 += __shfl_xor_sync(0xffffffffu, a1, 16);
    a2 += __shfl_xor_sync(0xffffffffu, a2, 16);
    a3 += __shfl_xor_sync(0xffffffffu, a3, 16);
    a4 += __shfl_xor_sync(0xffffffffu, a4, 16);
    a5 += __shfl_xor_sync(0xffffffffu, a5, 16);
    a6 += __shfl_xor_sync(0xffffffffu, a6, 16);
    a7 += __shfl_xor_sync(0xffffffffu, a7, 16);
    if (half == 0) {
        float inv = 1.0f / (float)max(deg, 1);
        union { uint4 u; __half2 h[4]; } pk;
        pk.h[0] = __floats2half2_rn(a0 * inv, a1 * inv);
        pk.h[1] = __floats2half2_rn(a2 * inv, a3 * inv);
        pk.h[2] = __floats2half2_rn(a4 * inv, a5 * inv);
        pk.h[3] = __floats2half2_rn(a6 * inv, a7 * inv);
        *reinterpret_cast<uint4*>(g_agg1 + (size_t)w * D_IN + l * 8) = pk.u;
    }
}

// ---------------- gather layer 2: warp per target, 4x8-lane groups -----------
__global__ void gather2() {
    int w = (blockIdx.x * blockDim.x + threadIdx.x) >> 5;   // target id
    if (w >= N_TGT) return;
    int lane = threadIdx.x & 31;
    int q = lane >> 3, l = lane & 7;
    int base = __ldg(g_roff2 + w);
    int deg  = __ldg(g_deg2 + w);
    float a0 = 0.f, a1 = 0.f, a2 = 0.f, a3 = 0.f,
          a4 = 0.f, a5 = 0.f, a6 = 0.f, a7 = 0.f;
    for (int j = q; j < deg; j += 4) {
        int s = __ldg(g_sorted2 + base + j);
        uint4 d = __ldg(reinterpret_cast<const uint4*>(g_hw + (size_t)s * D_OUT) + l);
        const __half2* hp = reinterpret_cast<const __half2*>(&d);
        float2 f0 = __half22float2(hp[0]), f1 = __half22float2(hp[1]);
        float2 f2 = __half22float2(hp[2]), f3 = __half22float2(hp[3]);
        a0 += f0.x; a1 += f0.y; a2 += f1.x; a3 += f1.y;
        a4 += f2.x; a5 += f2.y; a6 += f3.x; a7 += f3.y;
    }
#pragma unroll
    for (int m = 8; m <= 16; m <<= 1) {
        a0 += __shfl_xor_sync(0xffffffffu, a0, m);
        a1 += __shfl_xor_sync(0xffffffffu, a1, m);
        a2 += __shfl_xor_sync(0xffffffffu, a2, m);
        a3 += __shfl_xor_sync(0xffffffffu, a3, m);
        a4 += __shfl_xor_sync(0xffffffffu, a4, m);
        a5 += __shfl_xor_sync(0xffffffffu, a5, m);
        a6 += __shfl_xor_sync(0xffffffffu, a6, m);
        a7 += __shfl_xor_sync(0xffffffffu, a7, m);
    }
    if (q == 0) {
        float inv = 1.0f / (float)max(deg, 1);
        float* p = g_agg2 + (size_t)w * D_OUT + l * 8;
        float4 v0, v1;
        v0.x = a0 * inv; v0.y = a1 * inv; v0.z = a2 * inv; v0.w = a3 * inv;
        v1.x = a4 * inv; v1.y = a5 * inv; v1.z = a6 * inv; v1.w = a7 * inv;
        *reinterpret_cast<float4*>(p)     = v0;
        *reinterpret_cast<float4*>(p + 4) = v1;
    }
}

// ---------------- fp16 tensor-core GEMM (m16n8k16, fp32 accum) ----------------
// C[M,N] = [A0 | A1] @ W^T (+bias) (+ReLU).  A fp16 row-major, W fp16 [n][k].
// EPI 1: fp16 store to Ch16, rows < store_lim.   EPI 3: fp32 out + agg added.
// FUSE:  additionally hw = h_tile @ W2a (fp16 MMA) from smem-stashed h tile.
// Fragment map (g=lane>>2, t=lane&3):  a0=(g,2t:2t+1) a1=(g+8,·) a2=(g,8+2t:·)
// a3=(g+8,8+2t:·);  b0=(k=2t:2t+1,n=g) b1=(k=8+2t:·,n=g);  C same as k8.
__device__ __forceinline__ void mma_f16(float* c, const uint32_t* a,
                                        const uint32_t* b) {
    asm volatile(
        "mma.sync.aligned.m16n8k16.row.col.f32.f16.f16.f32 "
        "{%0,%1,%2,%3}, {%4,%5,%6,%7}, {%8,%9}, {%0,%1,%2,%3};"
        : "+f"(c[0]), "+f"(c[1]), "+f"(c[2]), "+f"(c[3])
        : "r"(a[0]), "r"(a[1]), "r"(a[2]), "r"(a[3]), "r"(b[0]), "r"(b[1]));
}

template <int BM, int BN, int BK, int WM, int WN, bool RELU, int EPI, bool FUSE>
__global__ void __launch_bounds__(256, 1)
gemm_f16(int M, int Nn, int K, int K1,
         const __half* __restrict__ A0, const __half* __restrict__ A1,
         const __half* __restrict__ W, const float* __restrict__ bias,
         float* __restrict__ Cf, __half* __restrict__ Ch16,
         const float* __restrict__ aggp,
         __half* __restrict__ hwp, const __half* __restrict__ w2h,
         int store_lim) {
    constexpr int STR = BK + 8;    // 72 halves; word addr (4g+t) conflict-free
    constexpr int AS = BM * STR;   // halves
    constexpr int BS = BN * STR;
    constexpr int STAGE = AS + BS;
    constexpr int WARPS_M = BM / WM;
    constexpr int MT = WM / 16, NT = WN / 8;

    extern __shared__ __half sm[];

    const int tid = threadIdx.x;
    const int warp = tid >> 5, lane = tid & 31;
    const int wm = warp % WARPS_M, wn = warp / WARPS_M;
    const int m0 = wm * WM, n0 = wn * WN;
    const int g = lane >> 2, t = lane & 3;
    const int row0 = blockIdx.y * BM, col0 = blockIdx.x * BN;
    const int K2s = K - K1;

    float acc[MT][NT][4];
#pragma unroll
    for (int i = 0; i < MT; i++)
#pragma unroll
        for (int j = 0; j < NT; j++)
#pragma unroll
            for (int r = 0; r < 4; r++) acc[i][j][r] = 0.f;

    auto load_stage = [&](int kt, int s) {
        __half* As = sm + s * STAGE;
        __half* Bs = As + AS;
        constexpr int A8 = BM * BK / 8;          // 16B chunks
#pragma unroll
        for (int p = 0; p < A8 / 256; p++) {
            int idx = tid + p * 256;
            int r = idx / (BK / 8);
            int kq = (idx % (BK / 8)) * 8;
            int gr = row0 + r;
            int cr = gr < M ? gr : M - 1;
            int gk = kt + kq;
            const __half* src = (gk < K1)
                ? (A0 + (size_t)cr * K1 + gk)
                : (A1 + (size_t)cr * K2s + (gk - K1));
            uint32_t dst = (uint32_t)__cvta_generic_to_shared(As + r * STR + kq);
            int sz = gr < M ? 16 : 0;
            asm volatile("cp.async.cg.shared.global [%0], [%1], 16, %2;"
                         :: "r"(dst), "l"(src), "r"(sz));
        }
        constexpr int B8 = BN * BK / 8;
#pragma unroll
        for (int p = 0; p < B8 / 256; p++) {
            int idx = tid + p * 256;
            int n = idx / (BK / 8);
            int kq = (idx % (BK / 8)) * 8;
            const __half* src = W + (size_t)(col0 + n) * K + kt + kq;
            uint32_t dst = (uint32_t)__cvta_generic_to_shared(Bs + n * STR + kq);
            asm volatile("cp.async.cg.shared.global [%0], [%1], 16;"
                         :: "r"(dst), "l"(src));
        }
        asm volatile("cp.async.commit_group;");
    };

    auto compute = [&](int s) {
        const __half* As = sm + s * STAGE;
        const __half* Bs = As + AS;
#pragma unroll
        for (int ks = 0; ks < BK / 16; ks++) {
            const int k0 = ks * 16;
            uint32_t af[MT][4], bf[NT][2];
#pragma unroll
            for (int i = 0; i < MT; i++) {
                const __half* a_lo = As + (m0 + 16 * i + g) * STR + k0 + 2 * t;
                const __half* a_hi = a_lo + 8 * STR;
                af[i][0] = *reinterpret_cast<const uint32_t*>(a_lo);
                af[i][1] = *reinterpret_cast<const uint32_t*>(a_hi);
                af[i][2] = *reinterpret_cast<const uint32_t*>(a_lo + 8);
                af[i][3] = *reinterpret_cast<const uint32_t*>(a_hi + 8);
            }
#pragma unroll
            for (int j = 0; j < NT; j++) {
                const __half* bp = Bs + (n0 + 8 * j + g) * STR + k0 + 2 * t;
                bf[j][0] = *reinterpret_cast<const uint32_t*>(bp);
                bf[j][1] = *reinterpret_cast<const uint32_t*>(bp + 8);
            }
#pragma unroll
            for (int i = 0; i < MT; i++)
#pragma unroll
                for (int j = 0; j < NT; j++)
                    mma_f16(acc[i][j], af[i], bf[j]);
        }
    };

    load_stage(0, 0);
    const int NKT = K / BK;
    for (int kt = 1; kt < NKT; kt++) {
        load_stage(kt * BK, kt & 1);
        asm volatile("cp.async.wait_group 1;");
        __syncthreads();
        compute((kt - 1) & 1);
        __syncthreads();
    }
    asm volatile("cp.async.wait_group 0;");
    __syncthreads();
    compute((NKT - 1) & 1);

    // ---- fused-epilogue smem (aliases the dead stage buffers) ----
    constexpr int HSTR = 264;   // halves; 264%64==8 -> words (4g+t) bijective
    __half* Hs  = sm;
    __half* W2s = Hs + BM * HSTR;

    if constexpr (FUSE) __syncthreads();          // stage smem reads done

    // ---- epilogue ----
#pragma unroll
    for (int i = 0; i < MT; i++) {
        const int r1 = row0 + m0 + 16 * i + g;
        const int r2 = r1 + 8;
#pragma unroll
        for (int j = 0; j < NT; j++) {
            const int col = col0 + n0 + 8 * j + 2 * t;
            float2 bb = *reinterpret_cast<const float2*>(bias + col);
            float2 v0, v1;
            v0.x = acc[i][j][0] + bb.x; v0.y = acc[i][j][1] + bb.y;
            v1.x = acc[i][j][2] + bb.x; v1.y = acc[i][j][3] + bb.y;
            if (EPI == 3) {   // add pre-normalized agg
                if (r1 < M) {
                    float2 a = *reinterpret_cast<const float2*>(
                        aggp + (size_t)r1 * Nn + col);
                    v0.x += a.x; v0.y += a.y;
                }
                if (r2 < M) {
                    float2 a = *reinterpret_cast<const float2*>(
                        aggp + (size_t)r2 * Nn + col);
                    v1.x += a.x; v1.y += a.y;
                }
            }
            if (RELU) {
                v0.x = fmaxf(v0.x, 0.f); v0.y = fmaxf(v0.y, 0.f);
                v1.x = fmaxf(v1.x, 0.f); v1.y = fmaxf(v1.y, 0.f);
            }
            if (EPI == 1) {   // fp16 h store (rows < store_lim)
                __half2 h0 = __floats2half2_rn(v0.x, v0.y);
                __half2 h1 = __floats2half2_rn(v1.x, v1.y);
                if (r1 < store_lim)
                    *reinterpret_cast<__half2*>(Ch16 + (size_t)r1 * Nn + col) = h0;
                if (r2 < store_lim)
                    *reinterpret_cast<__half2*>(Ch16 + (size_t)r2 * Nn + col) = h1;
                if constexpr (FUSE) {
                    const int lr = m0 + 16 * i + g, lc = n0 + 8 * j + 2 * t;
                    *reinterpret_cast<__half2*>(Hs + lr * HSTR + lc) = h0;
                    *reinterpret_cast<__half2*>(Hs + (lr + 8) * HSTR + lc) = h1;
                }
            } else {
                if (r1 < M)
                    *reinterpret_cast<float2*>(Cf + (size_t)r1 * Nn + col) = v0;
                if (r2 < M)
                    *reinterpret_cast<float2*>(Cf + (size_t)r2 * Nn + col) = v1;
            }
        }
    }

    if constexpr (FUSE) {
        // load W2a fp16 ([64][256] n-major) into W2s with pad
        const uint4* wsrc = reinterpret_cast<const uint4*>(w2h);
        for (int p = tid; p < (D_OUT * D_HID) / 8; p += 256) {
            int n = p >> 5;                 // 32 uint4 per 256-half row
            int kq = (p & 31) * 8;
            uint4 v = __ldg(wsrc + p);
            *reinterpret_cast<uint4*>(W2s + n * HSTR + kq) = v;
        }
        __syncthreads();

        // hw[128][64] = Hs[128][256] @ W2s^T, fp16 MMA m16n8k16
        const int m2 = (warp & 3) * 32;     // 4 warps along M
        const int n2 = (warp >> 2) * 32;    // 2 warps along N
        float hwacc[2][4][4];
#pragma unroll
        for (int i = 0; i < 2; i++)
#pragma unroll
            for (int j = 0; j < 4; j++)
#pragma unroll
                for (int r = 0; r < 4; r++) hwacc[i][j][r] = 0.f;

#pragma unroll
        for (int kk = 0; kk < D_HID; kk += 16) {
            uint32_t ha[2][4], hb[4][2];
#pragma unroll
            for (int i = 0; i < 2; i++) {
                const __half* b0 = Hs + (m2 + 16 * i + g) * HSTR + kk + 2 * t;
                const __half* b1 = b0 + 8 * HSTR;
                ha[i][0] = *reinterpret_cast<const uint32_t*>(b0);
                ha[i][1] = *reinterpret_cast<const uint32_t*>(b1);
                ha[i][2] = *reinterpret_cast<const uint32_t*>(b0 + 8);
                ha[i][3] = *reinterpret_cast<const uint32_t*>(b1 + 8);
            }
#pragma unroll
            for (int j = 0; j < 4; j++) {
                const __half* bp = W2s + (n2 + 8 * j + g) * HSTR + kk + 2 * t;
                hb[j][0] = *reinterpret_cast<const uint32_t*>(bp);
                hb[j][1] = *reinterpret_cast<const uint32_t*>(bp + 8);
            }
#pragma unroll
            for (int i = 0; i < 2; i++)
#pragma unroll
                for (int j = 0; j < 4; j++)
                    mma_f16(hwacc[i][j], ha[i], hb[j]);
        }

#pragma unroll
        for (int i = 0; i < 2; i++) {
            const int r1 = row0 + m2 + 16 * i + g;
            const int r2 = r1 + 8;
#pragma unroll
            for (int j = 0; j < 4; j++) {
                const int col = n2 + 8 * j + 2 * t;
                if (r1 < M)
                    *reinterpret_cast<__half2*>(hwp + (size_t)r1 * D_OUT + col) =
                        __floats2half2_rn(hwacc[i][j][0], hwacc[i][j][1]);
                if (r2 < M)
                    *reinterpret_cast<__half2*>(hwp + (size_t)r2 * D_OUT + col) =
                        __floats2half2_rn(hwacc[i][j][2], hwacc[i][j][3]);
            }
        }
    }
}

// ---------------- launch -----------------------------------------------------
extern "C" void kernel_launch(void* const* d_in, const int* in_sizes, int n_in,
                              void* d_out, int out_size) {
    const float* x   = (const float*)d_in[0];
    const int*   ei1 = (const int*)d_in[1];
    const int*   ei2 = (const int*)d_in[2];
    const float* Wl1 = (const float*)d_in[3];
    const float* Wr1 = (const float*)d_in[4];
    const float* b1  = (const float*)d_in[5];
    const float* Wl2 = (const float*)d_in[6];
    const float* Wr2 = (const float*)d_in[7];
    const float* b2  = (const float*)d_in[8];
    float* out = (float*)d_out;

    const int E1 = in_sizes[1] / 2;
    const int E2 = in_sizes[2] / 2;

    float *agg2;
    __half *agg1, *h, *hw, *xh, *w1h, *w2ah, *w2bh;
    int *deg1, *roff1, *woff1, *sums1, *sorted1;
    int *deg2, *roff2, *woff2, *sums2, *sorted2;
    cudaGetSymbolAddress((void**)&agg1,    g_agg1);
    cudaGetSymbolAddress((void**)&h,       g_h);
    cudaGetSymbolAddress((void**)&agg2,    g_agg2);
    cudaGetSymbolAddress((void**)&xh,      g_xh);
    cudaGetSymbolAddress((void**)&w1h,     g_W1h);
    cudaGetSymbolAddress((void**)&w2ah,    g_W2ah);
    cudaGetSymbolAddress((void**)&w2bh,    g_W2bh);
    cudaGetSymbolAddress((void**)&hw,      g_hw);
    cudaGetSymbolAddress((void**)&deg1,    g_deg1);
    cudaGetSymbolAddress((void**)&roff1,   g_roff1);
    cudaGetSymbolAddress((void**)&woff1,   g_woff1);
    cudaGetSymbolAddress((void**)&sums1,   g_sums1);
    cudaGetSymbolAddress((void**)&sorted1, g_sorted1);
    cudaGetSymbolAddress((void**)&deg2,    g_deg2);
    cudaGetSymbolAddress((void**)&roff2,   g_roff2);
    cudaGetSymbolAddress((void**)&woff2,   g_woff2);
    cudaGetSymbolAddress((void**)&sums2,   g_sums2);
    cudaGetSymbolAddress((void**)&sorted2, g_sorted2);

    // GEMM1: BM=128 BN=256 BK=64, stage=(128+256)*72*2 B, 2 stages = 110592 B
    // fused epilogue needs (128+64)*264*2 = 101376 B <= 110592 ✓
    const int smem1 = 2 * (128 + 256) * 72 * (int)sizeof(__half);
    cudaFuncSetAttribute(gemm_f16<128, 256, 64, 64, 64, true, 1, true>,
                         cudaFuncAttributeMaxDynamicSharedMemorySize, smem1);
    // GEMM_out: BM=128 BN=64 BK=64, 2 stages = (128+64)*72*2*2 = 55296 B
    const int smem2 = 2 * (128 + 64) * 72 * (int)sizeof(__half);
    cudaFuncSetAttribute(gemm_f16<128, 64, 64, 32, 32, false, 3, false>,
                         cudaFuncAttributeMaxDynamicSharedMemorySize, smem2);

    const int NB1 = (N_MID + 511) / 512;
    const int NB2 = (N_TGT + 511) / 512;

    // 1) prep  (prep_w coverage spans N_MID for deg re-zeroing every call)
    prep_x<<<(N_SRC * (D_IN / 4) + 255) / 256, 256>>>(x);
    {
        int cov = 2 * D_IN * D_HID;           // 65536
        if (cov < N_MID) cov = N_MID;         // 100000
        prep_w<<<(cov + 255) / 256, 256>>>(Wl1, Wr1, Wl2, Wr2);
    }

    // 2) CSR build, layer 1
    hist_kernel<<<(E1 + 255) / 256, 256>>>(ei1 + E1, E1, deg1);
    scan_block<<<NB1, 512>>>(deg1, N_MID, roff1, sums1);
    scan_sums<<<1, 512>>>(sums1, NB1);
    scan_add<<<NB1, 512>>>(roff1, woff1, sums1, N_MID);
    place_kernel<<<(E1 + 255) / 256, 256>>>(ei1, ei1 + E1, E1, woff1, sorted1);

    // 3) gather layer 1 -> agg1 fp16 (normalized)
    gather1<<<(N_MID * 32 + 255) / 256, 256>>>();

    // 4) h = relu([agg1 | xh] @ W1 + b1)  [N_MID, 256] fp16
    //    fused: h[:N_TGT] stored; hw = h @ Wl2 stored fp16 for ALL rows
    gemm_f16<128, 256, 64, 64, 64, true, 1, true>
        <<<dim3(1, (N_MID + 127) / 128), 256, smem1>>>(
            N_MID, D_HID, 2 * D_IN, D_IN, agg1, xh, w1h, b1,
            nullptr, h, nullptr, hw, w2ah, N_TGT);

    // 5) CSR build, layer 2
    hist_kernel<<<(E2 + 255) / 256, 256>>>(ei2 + E2, E2, deg2);
    scan_block<<<NB2, 512>>>(deg2, N_TGT, roff2, sums2);
    scan_sums<<<1, 512>>>(sums2, NB2);
    scan_add<<<NB2, 512>>>(roff2, woff2, sums2, N_TGT);
    place_kernel<<<(E2 + 255) / 256, 256>>>(ei2, ei2 + E2, E2, woff2, sorted2);

    // 6) gather layer 2 -> agg2 (normalized fp32)
    gather2<<<(N_TGT * 32 + 255) / 256, 256>>>();

    // 7) out = h[:N_TGT] @ Wr2 + b2 + agg2   [N_TGT, 64] fp32
    gemm_f16<128, 64, 64, 32, 32, false, 3, false>
        <<<dim3(1, (N_TGT + 127) / 128), 256, smem2>>>(
            N_TGT, D_OUT, D_HID, D_HID, h, h, w2bh, b2,
            out, nullptr, agg2, nullptr, nullptr, 0);
}